// round 1
// baseline (speedup 1.0000x reference)
#include <cuda_runtime.h>
#include <cuda_bf16.h>

// ---------------------------------------------------------------------------
// MSA: multi-head self-attention, B=2, S=4096, D_MODEL=768, H=12, d_k=64, fp32
//
// Pipeline (5 kernel launches):
//   1-3. gemm_bias_kernel<0>: Q/K/V = x @ W + b, written as [B, H, S, 64]
//   4.   attn_kernel: flash-attention (online softmax), ctx as [B, S, 768]
//   5.   gemm_bias_kernel<1>: out = ctx @ Wo + bo
// ---------------------------------------------------------------------------

#define D_MODEL 768
#define NHEAD   12
#define DK      64
#define BATCH   2
#define SEQ     4096
#define MROWS   (BATCH * SEQ)   // 8192

// Scratch (device globals: allocation-free per harness rules)
__device__ float g_Q[BATCH * NHEAD * SEQ * DK];
__device__ float g_K[BATCH * NHEAD * SEQ * DK];
__device__ float g_V[BATCH * NHEAD * SEQ * DK];
__device__ float g_ctx[MROWS * D_MODEL];

// ---------------------------------------------------------------------------
// GEMM + bias:  C = A[M,768] @ W[768,768] + bias
// MODE 0: scatter into [B, H, S, 64] (QKV);  MODE 1: row-major [M, 768]
// Tiles: BM=64, BN=64, BK=16; 256 threads; 4x4 microtile per thread.
// ---------------------------------------------------------------------------
#define GBM 64
#define GBN 64
#define GBK 16
#define GPAD 4

template <int MODE>
__global__ void __launch_bounds__(256) gemm_bias_kernel(
    const float* __restrict__ A, const float* __restrict__ W,
    const float* __restrict__ bias, float* __restrict__ C)
{
    const int N = D_MODEL, K = D_MODEL;
    __shared__ float As[GBK][GBM + GPAD];   // [k][m]
    __shared__ float Bs[GBK][GBN + GPAD];   // [k][n]

    const int tid = threadIdx.x;
    const int tx = tid & 15;          // 0..15 (n direction)
    const int ty = tid >> 4;          // 0..15 (m direction)
    const int m0 = blockIdx.y * GBM;
    const int n0 = blockIdx.x * GBN;

    // load assignments
    const int la_row = tid >> 2;            // 0..63  (m within tile)
    const int la_k   = (tid & 3) * 4;       // 0,4,8,12
    const int lb_k   = tid >> 4;            // 0..15
    const int lb_col = (tid & 15) * 4;      // 0..60

    float acc[4][4];
#pragma unroll
    for (int i = 0; i < 4; i++)
#pragma unroll
        for (int j = 0; j < 4; j++) acc[i][j] = 0.0f;

    for (int k0 = 0; k0 < K; k0 += GBK) {
        float4 av = *(const float4*)&A[(size_t)(m0 + la_row) * K + k0 + la_k];
        As[la_k + 0][la_row] = av.x;
        As[la_k + 1][la_row] = av.y;
        As[la_k + 2][la_row] = av.z;
        As[la_k + 3][la_row] = av.w;
        float4 bv = *(const float4*)&W[(size_t)(k0 + lb_k) * N + n0 + lb_col];
        *(float4*)&Bs[lb_k][lb_col] = bv;
        __syncthreads();

#pragma unroll
        for (int kk = 0; kk < GBK; kk++) {
            float4 a = *(const float4*)&As[kk][ty * 4];
            float4 b = *(const float4*)&Bs[kk][tx * 4];
            float ar[4] = {a.x, a.y, a.z, a.w};
            float br[4] = {b.x, b.y, b.z, b.w};
#pragma unroll
            for (int i = 0; i < 4; i++)
#pragma unroll
                for (int j = 0; j < 4; j++)
                    acc[i][j] += ar[i] * br[j];
        }
        __syncthreads();
    }

#pragma unroll
    for (int i = 0; i < 4; i++) {
        const int m = m0 + ty * 4 + i;
#pragma unroll
        for (int j = 0; j < 4; j++) {
            const int n = n0 + tx * 4 + j;
            float v = acc[i][j] + bias[n];
            if (MODE == 0) {
                // [B, H, S, 64] scatter
                int b = m >> 12;           // m / 4096
                int s = m & 4095;
                int h = n >> 6;            // n / 64
                int d = n & 63;
                C[(size_t)(((b * NHEAD + h) << 12) + s) * DK + d] = v;
            } else {
                C[(size_t)m * N + n] = v;
            }
        }
    }
}

// ---------------------------------------------------------------------------
// Flash attention: one CTA per (64-query tile, head, batch).
// smem: Q^T [64d][68], K^T [64d][68], P^T [64k][68], V [64k][64], m/l/alpha.
// 256 threads: 16x16 grid of 4x4 microtiles for both GEMMs; 8 warps own
// 8 query rows each for the online-softmax step.
// ---------------------------------------------------------------------------
#define ABQ 64
#define ABK 64
#define ASTR 68   // padded stride for transposed tiles

#define ATTN_SMEM_FLOATS (3 * 64 * ASTR + 64 * 64 + 3 * 64)
#define ATTN_SMEM_BYTES  (ATTN_SMEM_FLOATS * sizeof(float))

__global__ void __launch_bounds__(256) attn_kernel(
    const float* __restrict__ Q, const float* __restrict__ K,
    const float* __restrict__ V, float* __restrict__ ctx)
{
    extern __shared__ float sm[];
    float* Qs = sm;                       // [d][m], stride ASTR
    float* Ks = Qs + 64 * ASTR;           // [d][n], stride ASTR
    float* Ps = Ks + 64 * ASTR;           // [n][m], stride ASTR (scores^T)
    float* Vs = Ps + 64 * ASTR;           // [k][d], stride 64
    float* m_s  = Vs + 64 * 64;           // [64]
    float* l_s  = m_s + 64;               // [64]
    float* al_s = l_s + 64;               // [64]

    const int tid  = threadIdx.x;
    const int tx   = tid & 15;
    const int ty   = tid >> 4;
    const int lane = tid & 31;
    const int warp = tid >> 5;

    const int q0 = blockIdx.x * ABQ;
    const int h  = blockIdx.y;
    const int b  = blockIdx.z;
    const size_t head_off = (size_t)(b * NHEAD + h) * SEQ * DK;
    const float* Qb = Q + head_off;
    const float* Kb = K + head_off;
    const float* Vb = V + head_off;

    const float scale = 0.125f;  // 1/sqrt(64)

    // --- load Q tile, transposed + scaled ---
#pragma unroll
    for (int it = 0; it < 4; it++) {
        int idx = tid + it * 256;       // 0..1023
        int row = idx >> 4;             // 0..63 (query)
        int dq  = (idx & 15) * 4;       // 0..60
        float4 v = *(const float4*)&Qb[(size_t)(q0 + row) * DK + dq];
        Qs[(dq + 0) * ASTR + row] = v.x * scale;
        Qs[(dq + 1) * ASTR + row] = v.y * scale;
        Qs[(dq + 2) * ASTR + row] = v.z * scale;
        Qs[(dq + 3) * ASTR + row] = v.w * scale;
    }
    if (tid < 64) { m_s[tid] = -1e30f; l_s[tid] = 0.0f; }

    float o[4][4];
#pragma unroll
    for (int i = 0; i < 4; i++)
#pragma unroll
        for (int j = 0; j < 4; j++) o[i][j] = 0.0f;

    for (int kt = 0; kt < SEQ / ABK; kt++) {
        const int kbase = kt * ABK;
        // --- load K tile (transposed) and V tile (natural) ---
#pragma unroll
        for (int it = 0; it < 4; it++) {
            int idx = tid + it * 256;
            int row = idx >> 4;
            int dq  = (idx & 15) * 4;
            float4 kv = *(const float4*)&Kb[(size_t)(kbase + row) * DK + dq];
            Ks[(dq + 0) * ASTR + row] = kv.x;
            Ks[(dq + 1) * ASTR + row] = kv.y;
            Ks[(dq + 2) * ASTR + row] = kv.z;
            Ks[(dq + 3) * ASTR + row] = kv.w;
            float4 vv = *(const float4*)&Vb[(size_t)(kbase + row) * DK + dq];
            *(float4*)&Vs[row * 64 + dq] = vv;
        }
        __syncthreads();

        // --- scores: S^T[n][m] = sum_d K[n][d] * Q[m][d] (Q pre-scaled) ---
        float sacc[4][4];
#pragma unroll
        for (int i = 0; i < 4; i++)
#pragma unroll
            for (int j = 0; j < 4; j++) sacc[i][j] = 0.0f;

#pragma unroll 16
        for (int d = 0; d < 64; d++) {
            float4 a = *(const float4*)&Qs[d * ASTR + ty * 4];
            float4 bb = *(const float4*)&Ks[d * ASTR + tx * 4];
            float ar[4] = {a.x, a.y, a.z, a.w};
            float br[4] = {bb.x, bb.y, bb.z, bb.w};
#pragma unroll
            for (int i = 0; i < 4; i++)
#pragma unroll
                for (int j = 0; j < 4; j++)
                    sacc[i][j] += ar[i] * br[j];
        }
        // write scores^T: Ps[n][m]
#pragma unroll
        for (int j = 0; j < 4; j++) {
            float4 wv = make_float4(sacc[0][j], sacc[1][j], sacc[2][j], sacc[3][j]);
            *(float4*)&Ps[(tx * 4 + j) * ASTR + ty * 4] = wv;
        }
        __syncthreads();

        // --- online softmax: warp w owns query rows w*8 .. w*8+7 ---
#pragma unroll
        for (int rr = 0; rr < 8; rr++) {
            int r = warp * 8 + rr;
            float v0 = Ps[lane * ASTR + r];
            float v1 = Ps[(lane + 32) * ASTR + r];
            float mx = fmaxf(v0, v1);
#pragma unroll
            for (int off = 16; off > 0; off >>= 1)
                mx = fmaxf(mx, __shfl_xor_sync(0xffffffffu, mx, off));
            float m_old = m_s[r];
            float m_new = fmaxf(m_old, mx);
            float p0 = __expf(v0 - m_new);
            float p1 = __expf(v1 - m_new);
            float sum = p0 + p1;
#pragma unroll
            for (int off = 16; off > 0; off >>= 1)
                sum += __shfl_xor_sync(0xffffffffu, sum, off);
            Ps[lane * ASTR + r] = p0;
            Ps[(lane + 32) * ASTR + r] = p1;
            if (lane == 0) {
                float al = __expf(m_old - m_new);
                al_s[r] = al;
                l_s[r] = l_s[r] * al + sum;
                m_s[r] = m_new;
            }
        }
        __syncthreads();

        // --- rescale accumulators, then O += P @ V ---
        float arow[4];
#pragma unroll
        for (int i = 0; i < 4; i++) arow[i] = al_s[ty * 4 + i];
#pragma unroll
        for (int i = 0; i < 4; i++)
#pragma unroll
            for (int j = 0; j < 4; j++) o[i][j] *= arow[i];

#pragma unroll 16
        for (int k = 0; k < 64; k++) {
            float4 a = *(const float4*)&Ps[k * ASTR + ty * 4];
            float4 bb = *(const float4*)&Vs[k * 64 + tx * 4];
            float ar[4] = {a.x, a.y, a.z, a.w};
            float br[4] = {bb.x, bb.y, bb.z, bb.w};
#pragma unroll
            for (int i = 0; i < 4; i++)
#pragma unroll
                for (int j = 0; j < 4; j++)
                    o[i][j] += ar[i] * br[j];
        }
        __syncthreads();
    }

    // --- epilogue: normalize, write ctx as [B, S, 768] ---
#pragma unroll
    for (int i = 0; i < 4; i++) {
        int q = q0 + ty * 4 + i;
        float inv = 1.0f / l_s[ty * 4 + i];
#pragma unroll
        for (int j = 0; j < 4; j++) {
            int d = tx * 4 + j;
            ctx[(size_t)(b * SEQ + q) * D_MODEL + h * DK + d] = o[i][j] * inv;
        }
    }
}

// ---------------------------------------------------------------------------
// Launch
// ---------------------------------------------------------------------------
extern "C" void kernel_launch(void* const* d_in, const int* in_sizes, int n_in,
                              void* d_out, int out_size)
{
    const float* x  = (const float*)d_in[0];
    const float* Wq = (const float*)d_in[1];
    const float* bq = (const float*)d_in[2];
    const float* Wk = (const float*)d_in[3];
    const float* bk = (const float*)d_in[4];
    const float* Wv = (const float*)d_in[5];
    const float* bv = (const float*)d_in[6];
    const float* Wo = (const float*)d_in[7];
    const float* bo = (const float*)d_in[8];
    float* out = (float*)d_out;

    float *gq, *gk, *gv, *gctx;
    cudaGetSymbolAddress((void**)&gq,   g_Q);
    cudaGetSymbolAddress((void**)&gk,   g_K);
    cudaGetSymbolAddress((void**)&gv,   g_V);
    cudaGetSymbolAddress((void**)&gctx, g_ctx);

    cudaFuncSetAttribute(attn_kernel,
                         cudaFuncAttributeMaxDynamicSharedMemorySize,
                         (int)ATTN_SMEM_BYTES);

    dim3 gg(D_MODEL / GBN, MROWS / GBM);   // (12, 128)
    gemm_bias_kernel<0><<<gg, 256>>>(x, Wq, bq, gq);
    gemm_bias_kernel<0><<<gg, 256>>>(x, Wk, bk, gk);
    gemm_bias_kernel<0><<<gg, 256>>>(x, Wv, bv, gv);

    dim3 ga(SEQ / ABQ, NHEAD, BATCH);      // (64, 12, 2)
    attn_kernel<<<ga, 256, ATTN_SMEM_BYTES>>>(gq, gk, gv, gctx);

    gemm_bias_kernel<1><<<gg, 256>>>(gctx, Wo, bo, out);
}

// round 2
// speedup vs baseline: 2.0310x; 2.0310x over previous
#include <cuda_runtime.h>
#include <cuda_bf16.h>

// ---------------------------------------------------------------------------
// MSA fp32: B=2, S=4096, D=768, H=12, dk=64.
//   1-3. FFMA GEMM+bias (proven): Q/K/V = x@W+b  -> [B,H,S,64]
//   4.   flash attention with mma.sync tf32 (Q hi/lo split for accuracy)
//   5.   FFMA GEMM+bias: out = ctx@Wo+bo
// ---------------------------------------------------------------------------

#define D_MODEL 768
#define NHEAD   12
#define DK      64
#define BATCH   2
#define SEQ     4096
#define MROWS   (BATCH * SEQ)

__device__ float g_Q[BATCH * NHEAD * SEQ * DK];
__device__ float g_K[BATCH * NHEAD * SEQ * DK];
__device__ float g_V[BATCH * NHEAD * SEQ * DK];
__device__ float g_ctx[MROWS * D_MODEL];

// ---------------------------------------------------------------------------
// FFMA GEMM + bias (unchanged from R1, known-good)
// ---------------------------------------------------------------------------
#define GBM 64
#define GBN 64
#define GBK 16
#define GPAD 4

template <int MODE>
__global__ void __launch_bounds__(256) gemm_bias_kernel(
    const float* __restrict__ A, const float* __restrict__ W,
    const float* __restrict__ bias, float* __restrict__ C)
{
    const int N = D_MODEL, K = D_MODEL;
    __shared__ float As[GBK][GBM + GPAD];
    __shared__ float Bs[GBK][GBN + GPAD];

    const int tid = threadIdx.x;
    const int tx = tid & 15;
    const int ty = tid >> 4;
    const int m0 = blockIdx.y * GBM;
    const int n0 = blockIdx.x * GBN;

    const int la_row = tid >> 2;
    const int la_k   = (tid & 3) * 4;
    const int lb_k   = tid >> 4;
    const int lb_col = (tid & 15) * 4;

    float acc[4][4];
#pragma unroll
    for (int i = 0; i < 4; i++)
#pragma unroll
        for (int j = 0; j < 4; j++) acc[i][j] = 0.0f;

    for (int k0 = 0; k0 < K; k0 += GBK) {
        float4 av = *(const float4*)&A[(size_t)(m0 + la_row) * K + k0 + la_k];
        As[la_k + 0][la_row] = av.x;
        As[la_k + 1][la_row] = av.y;
        As[la_k + 2][la_row] = av.z;
        As[la_k + 3][la_row] = av.w;
        float4 bv = *(const float4*)&W[(size_t)(k0 + lb_k) * N + n0 + lb_col];
        *(float4*)&Bs[lb_k][lb_col] = bv;
        __syncthreads();

#pragma unroll
        for (int kk = 0; kk < GBK; kk++) {
            float4 a = *(const float4*)&As[kk][ty * 4];
            float4 b = *(const float4*)&Bs[kk][tx * 4];
            float ar[4] = {a.x, a.y, a.z, a.w};
            float br[4] = {b.x, b.y, b.z, b.w};
#pragma unroll
            for (int i = 0; i < 4; i++)
#pragma unroll
                for (int j = 0; j < 4; j++)
                    acc[i][j] += ar[i] * br[j];
        }
        __syncthreads();
    }

#pragma unroll
    for (int i = 0; i < 4; i++) {
        const int m = m0 + ty * 4 + i;
#pragma unroll
        for (int j = 0; j < 4; j++) {
            const int n = n0 + tx * 4 + j;
            float v = acc[i][j] + bias[n];
            if (MODE == 0) {
                int b = m >> 12;
                int s = m & 4095;
                int h = n >> 6;
                int d = n & 63;
                C[(size_t)(((b * NHEAD + h) << 12) + s) * DK + d] = v;
            } else {
                C[(size_t)m * N + n] = v;
            }
        }
    }
}

// ---------------------------------------------------------------------------
// tf32 mma flash attention
//   CTA = 128 threads (4 warps), 64 queries/CTA, 64 keys/iter, 64 iters.
//   Warp w owns query rows [16w, 16w+16). All GEMMs via mma.m16n8k8 tf32.
//   Q split hi+lo tf32 (score error ~= K rounding only).
//   smem fragment-packed layouts; Kp region aliased by P (scores->probs).
// ---------------------------------------------------------------------------
#define QT 64
#define KT 64
#define PSTR 72

// float-index offsets in dynamic smem
#define OFF_QHI 0
#define OFF_QLO 4096
#define OFF_KP  8192          // union with P
#define OFF_P   8192
#define OFF_VP  12800
#define ATTN_SMEM_FL 16896
#define ATTN_SMEM_BYTES (ATTN_SMEM_FL * 4)

__device__ __forceinline__ unsigned f2tf(float x) {
    unsigned r;
    asm("cvt.rna.tf32.f32 %0, %1;" : "=r"(r) : "f"(x));
    return r;
}

__device__ __forceinline__ void mma_tf32(float d[4], const unsigned a[4],
                                         const unsigned b[2]) {
    asm volatile(
        "mma.sync.aligned.m16n8k8.row.col.f32.tf32.tf32.f32 "
        "{%0,%1,%2,%3}, {%4,%5,%6,%7}, {%8,%9}, {%0,%1,%2,%3};"
        : "+f"(d[0]), "+f"(d[1]), "+f"(d[2]), "+f"(d[3])
        : "r"(a[0]), "r"(a[1]), "r"(a[2]), "r"(a[3]), "r"(b[0]), "r"(b[1]));
}

__global__ void __launch_bounds__(128) attn_kernel(
    const float* __restrict__ Q, const float* __restrict__ K,
    const float* __restrict__ V, float* __restrict__ ctx)
{
    extern __shared__ float sm[];
    const int tid  = threadIdx.x;
    const int lane = tid & 31;
    const int w    = tid >> 5;
    const int g    = lane >> 2;   // group (row within 8)
    const int qg   = lane & 3;    // thread-in-group (col base)

    const int q0 = blockIdx.x * QT;
    const int h  = blockIdx.y;
    const int b  = blockIdx.z;
    const size_t head_off = (size_t)(b * NHEAD + h) * SEQ * DK;
    const float* Qb = Q + head_off;
    const float* Kb = K + head_off;
    const float* Vb = V + head_off;

    // ---- load + pack Q (once), scaled by 1/8, hi/lo tf32 split ----
#pragma unroll
    for (int i = 0; i < 8; i++) {
        int idx = i * 128 + tid;
        int q  = idx >> 4;
        int d0 = (idx & 15) * 4;
        float4 v = *(const float4*)&Qb[(size_t)(q0 + q) * DK + d0];
        float vv[4] = {v.x * 0.125f, v.y * 0.125f, v.z * 0.125f, v.w * 0.125f};
        int wq = q >> 4;
        int rw = q & 15;
        int gq = rw & 7;
        int rb = rw >> 3;                       // 0 -> a0/a2, 1 -> a1/a3
        int ks = d0 >> 3;
        int rr = rb + 2 * ((d0 & 7) >> 2);      // register slot 0..3
        int base = (wq * 8 + ks) * 128 + rr;
#pragma unroll
        for (int j = 0; j < 4; j++) {
            unsigned hb = f2tf(vv[j]);
            float hf = __uint_as_float(hb);
            unsigned lb = f2tf(vv[j] - hf);
            int a = base + (gq * 4 + j) * 4;
            sm[OFF_QHI + a] = hf;
            sm[OFF_QLO + a] = __uint_as_float(lb);
        }
    }

    float m0 = -1e30f, m1 = -1e30f, l0 = 0.0f, l1 = 0.0f;
    float o[8][4];
#pragma unroll
    for (int nt = 0; nt < 8; nt++)
#pragma unroll
        for (int j = 0; j < 4; j++) o[nt][j] = 0.0f;

    for (int kt = 0; kt < SEQ / KT; kt++) {
        const int kbase = kt * KT;
        __syncthreads();   // prior PV reads of P/Vp complete

        // ---- repack K and V tiles into fragment layouts (tf32) ----
#pragma unroll
        for (int i = 0; i < 8; i++) {
            int idx = i * 128 + tid;
            int row = idx >> 4;
            int d0  = (idx & 15) * 4;
            // K: B-frag for scores. lane=(n&7)*4+(d&3), reg=(d&7)>>2, sw by ks
            {
                float4 kv = *(const float4*)&Kb[(size_t)(kbase + row) * DK + d0];
                float kk[4] = {kv.x, kv.y, kv.z, kv.w};
                int ks = d0 >> 3, r = (d0 & 7) >> 2, nt = row >> 3;
                int lb = (row & 7) * 4, sw = ks << 2;
                int base = OFF_KP + (ks * 8 + nt) * 64;
#pragma unroll
                for (int j = 0; j < 4; j++)
                    sm[base + (((lb + j) ^ sw) << 1) + r] =
                        __uint_as_float(f2tf(kk[j]));
            }
            // V: B-frag for PV. lane=(d&7)*4+(k&3), reg=(k&7)>>2, sw by nt
            {
                float4 vv4 = *(const float4*)&Vb[(size_t)(kbase + row) * DK + d0];
                float vv[4] = {vv4.x, vv4.y, vv4.z, vv4.w};
                int ks = row >> 3, r = (row & 7) >> 2, nt = d0 >> 3;
                int sw = nt << 2;
                int base = OFF_VP + (ks * 8 + nt) * 64;
#pragma unroll
                for (int j = 0; j < 4; j++) {
                    int lv = ((d0 & 7) + j) * 4 + (row & 3);
                    sm[base + ((lv ^ sw) << 1) + r] =
                        __uint_as_float(f2tf(vv[j]));
                }
            }
        }
        __syncthreads();

        // ---- scores: S(16x64 per warp) = Qhi*K^T + Qlo*K^T ----
        float s[8][4];
#pragma unroll
        for (int nt = 0; nt < 8; nt++)
#pragma unroll
            for (int j = 0; j < 4; j++) s[nt][j] = 0.0f;

#pragma unroll
        for (int ks = 0; ks < 8; ks++) {
            float4 ah4 = *(const float4*)&sm[OFF_QHI + (w * 8 + ks) * 128 + lane * 4];
            float4 al4 = *(const float4*)&sm[OFF_QLO + (w * 8 + ks) * 128 + lane * 4];
            unsigned ah[4] = {__float_as_uint(ah4.x), __float_as_uint(ah4.y),
                              __float_as_uint(ah4.z), __float_as_uint(ah4.w)};
            unsigned al[4] = {__float_as_uint(al4.x), __float_as_uint(al4.y),
                              __float_as_uint(al4.z), __float_as_uint(al4.w)};
            int swl = (lane ^ (ks << 2)) << 1;
#pragma unroll
            for (int nt = 0; nt < 8; nt++) {
                float2 bf = *(const float2*)&sm[OFF_KP + (ks * 8 + nt) * 64 + swl];
                unsigned bb[2] = {__float_as_uint(bf.x), __float_as_uint(bf.y)};
                mma_tf32(s[nt], al, bb);
                mma_tf32(s[nt], ah, bb);
            }
        }

        // ---- online softmax (registers + quad shuffles) ----
        float mx0 = -1e30f, mx1 = -1e30f;
#pragma unroll
        for (int nt = 0; nt < 8; nt++) {
            mx0 = fmaxf(mx0, fmaxf(s[nt][0], s[nt][1]));
            mx1 = fmaxf(mx1, fmaxf(s[nt][2], s[nt][3]));
        }
        mx0 = fmaxf(mx0, __shfl_xor_sync(0xffffffffu, mx0, 1));
        mx0 = fmaxf(mx0, __shfl_xor_sync(0xffffffffu, mx0, 2));
        mx1 = fmaxf(mx1, __shfl_xor_sync(0xffffffffu, mx1, 1));
        mx1 = fmaxf(mx1, __shfl_xor_sync(0xffffffffu, mx1, 2));

        float mn0 = fmaxf(m0, mx0), mn1 = fmaxf(m1, mx1);
        float al0 = __expf(m0 - mn0), al1 = __expf(m1 - mn1);
        m0 = mn0; m1 = mn1;

        float rs0 = 0.0f, rs1 = 0.0f;
#pragma unroll
        for (int nt = 0; nt < 8; nt++) {
            s[nt][0] = __expf(s[nt][0] - mn0);
            s[nt][1] = __expf(s[nt][1] - mn0);
            s[nt][2] = __expf(s[nt][2] - mn1);
            s[nt][3] = __expf(s[nt][3] - mn1);
            rs0 += s[nt][0] + s[nt][1];
            rs1 += s[nt][2] + s[nt][3];
        }
        rs0 += __shfl_xor_sync(0xffffffffu, rs0, 1);
        rs0 += __shfl_xor_sync(0xffffffffu, rs0, 2);
        rs1 += __shfl_xor_sync(0xffffffffu, rs1, 1);
        rs1 += __shfl_xor_sync(0xffffffffu, rs1, 2);
        l0 = l0 * al0 + rs0;
        l1 = l1 * al1 + rs1;

        // rescale O
#pragma unroll
        for (int nt = 0; nt < 8; nt++) {
            o[nt][0] *= al0; o[nt][1] *= al0;
            o[nt][2] *= al1; o[nt][3] *= al1;
        }

        __syncthreads();   // all warps done reading Kp -> safe to write P

        // ---- write P (tf32) to per-warp region (aliases Kp) ----
        float* Pw = &sm[OFF_P + w * 16 * PSTR];
#pragma unroll
        for (int nt = 0; nt < 8; nt++) {
            float2 p01 = make_float2(__uint_as_float(f2tf(s[nt][0])),
                                     __uint_as_float(f2tf(s[nt][1])));
            float2 p23 = make_float2(__uint_as_float(f2tf(s[nt][2])),
                                     __uint_as_float(f2tf(s[nt][3])));
            *(float2*)&Pw[g * PSTR + nt * 8 + 2 * qg] = p01;
            *(float2*)&Pw[(g + 8) * PSTR + nt * 8 + 2 * qg] = p23;
        }
        __syncwarp();

        // ---- O += P @ V ----
#pragma unroll
        for (int ks = 0; ks < 8; ks++) {
            unsigned a[4] = {
                __float_as_uint(Pw[g * PSTR + ks * 8 + qg]),
                __float_as_uint(Pw[(g + 8) * PSTR + ks * 8 + qg]),
                __float_as_uint(Pw[g * PSTR + ks * 8 + qg + 4]),
                __float_as_uint(Pw[(g + 8) * PSTR + ks * 8 + qg + 4])};
#pragma unroll
            for (int nt = 0; nt < 8; nt++) {
                float2 bf = *(const float2*)
                    &sm[OFF_VP + (ks * 8 + nt) * 64 + ((lane ^ (nt << 2)) << 1)];
                unsigned bb[2] = {__float_as_uint(bf.x), __float_as_uint(bf.y)};
                mma_tf32(o[nt], a, bb);
            }
        }
    }

    // ---- epilogue: normalize, write ctx [B,S,768] ----
    float inv0 = 1.0f / l0, inv1 = 1.0f / l1;
    const int qa = q0 + w * 16 + g;
    const int qb2 = qa + 8;
    const size_t rowA = ((size_t)(b * SEQ) + qa) * D_MODEL + h * DK;
    const size_t rowB = ((size_t)(b * SEQ) + qb2) * D_MODEL + h * DK;
#pragma unroll
    for (int nt = 0; nt < 8; nt++) {
        int c = nt * 8 + 2 * qg;
        *(float2*)&ctx[rowA + c] = make_float2(o[nt][0] * inv0, o[nt][1] * inv0);
        *(float2*)&ctx[rowB + c] = make_float2(o[nt][2] * inv1, o[nt][3] * inv1);
    }
}

// ---------------------------------------------------------------------------
// Launch
// ---------------------------------------------------------------------------
extern "C" void kernel_launch(void* const* d_in, const int* in_sizes, int n_in,
                              void* d_out, int out_size)
{
    const float* x  = (const float*)d_in[0];
    const float* Wq = (const float*)d_in[1];
    const float* bq = (const float*)d_in[2];
    const float* Wk = (const float*)d_in[3];
    const float* bk = (const float*)d_in[4];
    const float* Wv = (const float*)d_in[5];
    const float* bv = (const float*)d_in[6];
    const float* Wo = (const float*)d_in[7];
    const float* bo = (const float*)d_in[8];
    float* out = (float*)d_out;

    float *gq, *gk, *gv, *gctx;
    cudaGetSymbolAddress((void**)&gq,   g_Q);
    cudaGetSymbolAddress((void**)&gk,   g_K);
    cudaGetSymbolAddress((void**)&gv,   g_V);
    cudaGetSymbolAddress((void**)&gctx, g_ctx);

    cudaFuncSetAttribute(attn_kernel,
                         cudaFuncAttributeMaxDynamicSharedMemorySize,
                         ATTN_SMEM_BYTES);

    dim3 gg(D_MODEL / GBN, MROWS / GBM);
    gemm_bias_kernel<0><<<gg, 256>>>(x, Wq, bq, gq);
    gemm_bias_kernel<0><<<gg, 256>>>(x, Wk, bk, gk);
    gemm_bias_kernel<0><<<gg, 256>>>(x, Wv, bv, gv);

    dim3 ga(SEQ / QT, NHEAD, BATCH);   // (64, 12, 2)
    attn_kernel<<<ga, 128, ATTN_SMEM_BYTES>>>(gq, gk, gv, gctx);

    gemm_bias_kernel<1><<<gg, 256>>>(gctx, Wo, bo, out);
}

// round 3
// speedup vs baseline: 3.3681x; 1.6583x over previous
#include <cuda_runtime.h>

// ---------------------------------------------------------------------------
// MSA fp32: B=2, S=4096, D=768, H=12, dk=64 — all GEMMs on tf32 mma.sync.
// Launches:
//   repack_A(x)        x -> hi/lo A-fragment tiles
//   repack_W x4        W -> tf32 B-fragment tiles
//   mma_gemm<Q/K/V>    Q normal [B,H,S,64]; K/V written in attn frag layout
//   attn_kernel        flash attention, cp.async double-buffered, P in regs
//   repack_A(ctx)      ctx -> hi/lo A-fragment tiles (reuses buffer)
//   mma_gemm<OUT>      out = ctx @ Wo + bo
// ---------------------------------------------------------------------------

#define D_MODEL 768
#define NHEAD   12
#define DK      64
#define BATCH   2
#define SEQ     4096
#define MROWS   8192
#define KTILES  48      // 768/16
#define NTILES  12      // 768/64
#define MTILES  128     // 8192/64

__device__ float g_Q  [BATCH * NHEAD * SEQ * DK];
__device__ float g_Kp [BATCH * NHEAD * SEQ * DK];
__device__ float g_Vp [BATCH * NHEAD * SEQ * DK];
__device__ float g_ctx[MROWS * D_MODEL];
__device__ float g_Apk[(size_t)MROWS * D_MODEL * 2];       // hi/lo packed A
__device__ float g_Wpk[4 * D_MODEL * D_MODEL];             // packed W x4

// ---------------------------------------------------------------------------
// helpers
// ---------------------------------------------------------------------------
__device__ __forceinline__ unsigned f2tf(float x) {
    unsigned r;
    asm("cvt.rna.tf32.f32 %0, %1;" : "=r"(r) : "f"(x));
    return r;
}

__device__ __forceinline__ void mma_tf32(float d[4], const unsigned a[4],
                                         const unsigned b[2]) {
    asm volatile(
        "mma.sync.aligned.m16n8k8.row.col.f32.tf32.tf32.f32 "
        "{%0,%1,%2,%3}, {%4,%5,%6,%7}, {%8,%9}, {%0,%1,%2,%3};"
        : "+f"(d[0]), "+f"(d[1]), "+f"(d[2]), "+f"(d[3])
        : "r"(a[0]), "r"(a[1]), "r"(a[2]), "r"(a[3]), "r"(b[0]), "r"(b[1]));
}

__device__ __forceinline__ void cp_async16(unsigned s_addr, const void* g_ptr) {
    asm volatile("cp.async.cg.shared.global [%0], [%1], 16;"
                 :: "r"(s_addr), "l"(g_ptr) : "memory");
}
__device__ __forceinline__ void cp_commit() {
    asm volatile("cp.async.commit_group;" ::: "memory");
}
__device__ __forceinline__ void cp_wait0() {
    asm volatile("cp.async.wait_group 0;" ::: "memory");
}

// A-fragment pack index (64 rows x 16 k per tile, hi half): 0..1023
__device__ __forceinline__ int a_pack_idx(int q, int kk) {
    return ((q >> 4) * 2 + (kk >> 3)) * 128 + ((q & 7) * 4 + (kk & 3)) * 4 +
           ((q & 15) >> 3) + 2 * ((kk & 7) >> 2);
}
// B-fragment pack index (16 k x 64 n per tile): 0..1023
__device__ __forceinline__ int b_pack_idx(int kk, int nn) {
    int ks = kk >> 3, nt = nn >> 3;
    int lane = (nn & 7) * 4 + (kk & 3);
    int r = (kk & 7) >> 2;
    return (ks * 8 + nt) * 64 + ((lane ^ (ks << 2)) << 1) + r;
}
// attention K fragment (64 keys x 64 d), WITH key permutation within 8-groups
__device__ __forceinline__ int kattn_idx(int key, int d) {
    int r8 = key & 7;
    int col8 = (r8 < 4) ? (r8 << 1) : (((r8 - 4) << 1) | 1);
    int ks = d >> 3, nt = key >> 3;
    int lane = col8 * 4 + (d & 3);
    int r = (d & 7) >> 2;
    return (ks * 8 + nt) * 64 + ((lane ^ (ks << 2)) << 1) + r;
}
// attention V fragment (64 keys x 64 d), natural key order
__device__ __forceinline__ int vattn_idx(int key, int d) {
    int ks = key >> 3, nt = d >> 3;
    int lv = (d & 7) * 4 + (key & 3);
    int r = (key & 7) >> 2;
    return (ks * 8 + nt) * 64 + ((lv ^ (nt << 2)) << 1) + r;
}

// ---------------------------------------------------------------------------
// repack_A: [8192,768] fp32 -> per-(64x16)-tile hi/lo fragment layout
// ---------------------------------------------------------------------------
__global__ void __launch_bounds__(256) repack_A(const float* __restrict__ A,
                                                float* __restrict__ dst) {
    int idx = blockIdx.x * 256 + threadIdx.x;       // one float4 each
    int m  = idx / 192;
    int k4 = (idx % 192) * 4;
    float4 v = *(const float4*)&A[(size_t)m * D_MODEL + k4];
    float vv[4] = {v.x, v.y, v.z, v.w};
    int mtile = m >> 6, q = m & 63;
#pragma unroll
    for (int j = 0; j < 4; j++) {
        int k = k4 + j;
        size_t base = ((size_t)mtile * KTILES + (k >> 4)) * 2048 +
                      a_pack_idx(q, k & 15);
        unsigned hb = f2tf(vv[j]);
        float hf = __uint_as_float(hb);
        dst[base]        = hf;
        dst[base + 1024] = __uint_as_float(f2tf(vv[j] - hf));
    }
}

// ---------------------------------------------------------------------------
// repack_W: [768,768] fp32 -> per-(16x64)-tile tf32 B-fragment layout
// ---------------------------------------------------------------------------
__global__ void __launch_bounds__(256) repack_W(const float* __restrict__ W,
                                                float* __restrict__ dst) {
    int idx = blockIdx.x * 256 + threadIdx.x;       // one float4 of n each
    int k  = idx / 192;
    int n4 = (idx % 192) * 4;
    float4 v = *(const float4*)&W[(size_t)k * D_MODEL + n4];
    float vv[4] = {v.x, v.y, v.z, v.w};
#pragma unroll
    for (int j = 0; j < 4; j++) {
        int n = n4 + j;
        size_t base = ((size_t)(k >> 4) * NTILES + (n >> 6)) * 1024 +
                      b_pack_idx(k & 15, n & 63);
        dst[base] = __uint_as_float(f2tf(vv[j]));
    }
}

// ---------------------------------------------------------------------------
// mma GEMM: C[8192,768] = A @ W + bias.  CTA = 64m x 64n, 4 warps, BK=16,
// cp.async double-buffered.  MODE: 0=Q-layout, 1=K-frag, 2=V-frag, 3=row-major
// ---------------------------------------------------------------------------
template <int MODE>
__global__ void __launch_bounds__(128) mma_gemm(
    const float* __restrict__ Apk, const float* __restrict__ Bpk,
    const float* __restrict__ bias, float* __restrict__ C)
{
    __shared__ float As[2][2048];
    __shared__ float Bs[2][1024];

    const int tid = threadIdx.x;
    const int lane = tid & 31;
    const int w = tid >> 5;
    const int g = lane >> 2;
    const int qg = lane & 3;
    const int ntile = blockIdx.x;
    const int mtile = blockIdx.y;

    const float* Abase = Apk + (size_t)mtile * KTILES * 2048;

    float c[8][4];
#pragma unroll
    for (int nt = 0; nt < 8; nt++)
#pragma unroll
        for (int j = 0; j < 4; j++) c[nt][j] = 0.0f;

    unsigned sA0 = (unsigned)__cvta_generic_to_shared(&As[0][0]);
    unsigned sA1 = (unsigned)__cvta_generic_to_shared(&As[1][0]);
    unsigned sB0 = (unsigned)__cvta_generic_to_shared(&Bs[0][0]);
    unsigned sB1 = (unsigned)__cvta_generic_to_shared(&Bs[1][0]);

#define GEMM_ISSUE(KT)                                                        \
    do {                                                                      \
        int _b = (KT) & 1;                                                    \
        unsigned _sa = _b ? sA1 : sA0;                                        \
        unsigned _sb = _b ? sB1 : sB0;                                        \
        const float4* _ga = (const float4*)(Abase + (size_t)(KT) * 2048);     \
        const float4* _gb = (const float4*)(Bpk +                             \
                            ((size_t)(KT) * NTILES + ntile) * 1024);          \
        cp_async16(_sa + (unsigned)(tid * 16),        _ga + tid);             \
        cp_async16(_sa + (unsigned)(tid * 16) + 2048, _ga + 128 + tid);       \
        cp_async16(_sa + (unsigned)(tid * 16) + 4096, _ga + 256 + tid);       \
        cp_async16(_sa + (unsigned)(tid * 16) + 6144, _ga + 384 + tid);       \
        cp_async16(_sb + (unsigned)(tid * 16),        _gb + tid);             \
        cp_async16(_sb + (unsigned)(tid * 16) + 2048, _gb + 128 + tid);       \
        cp_commit();                                                          \
    } while (0)

    GEMM_ISSUE(0);

    for (int kt = 0; kt < KTILES; kt++) {
        cp_wait0();
        __syncthreads();
        if (kt + 1 < KTILES) GEMM_ISSUE(kt + 1);
        const int buf = kt & 1;
#pragma unroll
        for (int ks = 0; ks < 2; ks++) {
            float4 ah4 = *(const float4*)&As[buf][(w * 2 + ks) * 128 + lane * 4];
            float4 al4 = *(const float4*)&As[buf][1024 + (w * 2 + ks) * 128 + lane * 4];
            unsigned ah[4] = {__float_as_uint(ah4.x), __float_as_uint(ah4.y),
                              __float_as_uint(ah4.z), __float_as_uint(ah4.w)};
            unsigned al[4] = {__float_as_uint(al4.x), __float_as_uint(al4.y),
                              __float_as_uint(al4.z), __float_as_uint(al4.w)};
            int swl = (lane ^ (ks << 2)) << 1;
#pragma unroll
            for (int nt = 0; nt < 8; nt++) {
                float2 bf = *(const float2*)&Bs[buf][(ks * 8 + nt) * 64 + swl];
                unsigned bb[2] = {__float_as_uint(bf.x), __float_as_uint(bf.y)};
                mma_tf32(c[nt], al, bb);
                mma_tf32(c[nt], ah, bb);
            }
        }
        __syncthreads();
    }

    // epilogue
#pragma unroll
    for (int nt = 0; nt < 8; nt++) {
#pragma unroll
        for (int j = 0; j < 4; j++) {
            int m_local = w * 16 + g + ((j >= 2) ? 8 : 0);
            int n_local = nt * 8 + 2 * qg + (j & 1);
            float v = c[nt][j] + bias[ntile * 64 + n_local];
            if (MODE == 0) {
                int m = mtile * 64 + m_local;
                int b = m >> 12, s = m & 4095;
                C[(size_t)(((b * NHEAD + ntile) << 12) + s) * DK + n_local] = v;
            } else if (MODE == 1) {
                int b = mtile >> 6, kt = mtile & 63;
                size_t base = ((size_t)(b * NHEAD + ntile) * 64 + kt) * 4096;
                C[base + kattn_idx(m_local, n_local)] =
                    __uint_as_float(f2tf(v));
            } else if (MODE == 2) {
                int b = mtile >> 6, kt = mtile & 63;
                size_t base = ((size_t)(b * NHEAD + ntile) * 64 + kt) * 4096;
                C[base + vattn_idx(m_local, n_local)] =
                    __uint_as_float(f2tf(v));
            } else {
                int m = mtile * 64 + m_local;
                C[(size_t)m * D_MODEL + ntile * 64 + n_local] = v;
            }
        }
    }
#undef GEMM_ISSUE
}

// ---------------------------------------------------------------------------
// flash attention: 128 thr (4 warps), 64 q/CTA, 64 keys/iter.
// K/V pre-packed tf32 fragments in global; cp.async double-buffered.
// Key permutation makes score C-frag == PV A-frag (P never leaves registers).
// ---------------------------------------------------------------------------
#define OFF_QHI 0
#define OFF_QLO 4096
#define OFF_K0  8192
#define OFF_V0  16384
#define ATTN_SMEM_BYTES (24576 * 4)

__global__ void __launch_bounds__(128) attn_kernel(
    const float* __restrict__ Q, const float* __restrict__ Kp,
    const float* __restrict__ Vp, float* __restrict__ ctx)
{
    extern __shared__ float sm[];
    const int tid  = threadIdx.x;
    const int lane = tid & 31;
    const int w    = tid >> 5;
    const int g    = lane >> 2;
    const int qg   = lane & 3;

    const int q0 = blockIdx.x * 64;
    const int h  = blockIdx.y;
    const int b  = blockIdx.z;
    const size_t head_off = (size_t)(b * NHEAD + h) * SEQ * DK;
    const float* Qb = Q + head_off;
    const float* Kh = Kp + head_off;   // [kt][4096] packed
    const float* Vh = Vp + head_off;

    unsigned smK = (unsigned)__cvta_generic_to_shared(sm) + OFF_K0 * 4;
    unsigned smV = (unsigned)__cvta_generic_to_shared(sm) + OFF_V0 * 4;

#define ATTN_ISSUE(KT)                                                        \
    do {                                                                      \
        int _b2 = (KT) & 1;                                                   \
        const float4* _gk = (const float4*)(Kh + (size_t)(KT) * 4096);        \
        const float4* _gv = (const float4*)(Vh + (size_t)(KT) * 4096);        \
        unsigned _sk = smK + _b2 * 16384;                                     \
        unsigned _sv = smV + _b2 * 16384;                                     \
        _Pragma("unroll")                                                     \
        for (int _i = 0; _i < 8; _i++) {                                      \
            cp_async16(_sk + (unsigned)((_i * 128 + tid) * 16),               \
                       _gk + _i * 128 + tid);                                 \
            cp_async16(_sv + (unsigned)((_i * 128 + tid) * 16),               \
                       _gv + _i * 128 + tid);                                 \
        }                                                                     \
        cp_commit();                                                          \
    } while (0)

    // ---- pack Q (hi/lo tf32, scaled 1/8) ----
#pragma unroll
    for (int i = 0; i < 8; i++) {
        int idx = i * 128 + tid;
        int q  = idx >> 4;
        int d0 = (idx & 15) * 4;
        float4 v = *(const float4*)&Qb[(size_t)(q0 + q) * DK + d0];
        float vv[4] = {v.x * 0.125f, v.y * 0.125f, v.z * 0.125f, v.w * 0.125f};
        int base = ((q >> 4) * 8 + (d0 >> 3)) * 128 +
                   ((q & 15) >> 3) + 2 * ((d0 & 7) >> 2);
#pragma unroll
        for (int j = 0; j < 4; j++) {
            unsigned hb = f2tf(vv[j]);
            float hf = __uint_as_float(hb);
            int a = base + ((q & 7) * 4 + j) * 4;
            sm[OFF_QHI + a] = hf;
            sm[OFF_QLO + a] = __uint_as_float(f2tf(vv[j] - hf));
        }
    }

    ATTN_ISSUE(0);

    float m0 = -1e30f, m1 = -1e30f, l0 = 0.0f, l1 = 0.0f;
    float o[8][4];
#pragma unroll
    for (int nt = 0; nt < 8; nt++)
#pragma unroll
        for (int j = 0; j < 4; j++) o[nt][j] = 0.0f;

    for (int kt = 0; kt < SEQ / 64; kt++) {
        cp_wait0();
        __syncthreads();                 // tile kt visible; prev reads done
        if (kt + 1 < SEQ / 64) ATTN_ISSUE(kt + 1);

        const int kbuf = OFF_K0 + (kt & 1) * 4096;
        const int vbuf = OFF_V0 + (kt & 1) * 4096;

        // ---- scores (hi + lo) ----
        float s[8][4];
#pragma unroll
        for (int nt = 0; nt < 8; nt++)
#pragma unroll
            for (int j = 0; j < 4; j++) s[nt][j] = 0.0f;

#pragma unroll
        for (int ks = 0; ks < 8; ks++) {
            float4 ah4 = *(const float4*)&sm[OFF_QHI + (w * 8 + ks) * 128 + lane * 4];
            float4 al4 = *(const float4*)&sm[OFF_QLO + (w * 8 + ks) * 128 + lane * 4];
            unsigned ah[4] = {__float_as_uint(ah4.x), __float_as_uint(ah4.y),
                              __float_as_uint(ah4.z), __float_as_uint(ah4.w)};
            unsigned al[4] = {__float_as_uint(al4.x), __float_as_uint(al4.y),
                              __float_as_uint(al4.z), __float_as_uint(al4.w)};
            int swl = (lane ^ (ks << 2)) << 1;
#pragma unroll
            for (int nt = 0; nt < 8; nt++) {
                float2 bf = *(const float2*)&sm[kbuf + (ks * 8 + nt) * 64 + swl];
                unsigned bb[2] = {__float_as_uint(bf.x), __float_as_uint(bf.y)};
                mma_tf32(s[nt], al, bb);
                mma_tf32(s[nt], ah, bb);
            }
        }

        // ---- online softmax (cols are permuted keys; max/sum invariant) ----
        float mx0 = -1e30f, mx1 = -1e30f;
#pragma unroll
        for (int nt = 0; nt < 8; nt++) {
            mx0 = fmaxf(mx0, fmaxf(s[nt][0], s[nt][1]));
            mx1 = fmaxf(mx1, fmaxf(s[nt][2], s[nt][3]));
        }
        mx0 = fmaxf(mx0, __shfl_xor_sync(0xffffffffu, mx0, 1));
        mx0 = fmaxf(mx0, __shfl_xor_sync(0xffffffffu, mx0, 2));
        mx1 = fmaxf(mx1, __shfl_xor_sync(0xffffffffu, mx1, 1));
        mx1 = fmaxf(mx1, __shfl_xor_sync(0xffffffffu, mx1, 2));

        float mn0 = fmaxf(m0, mx0), mn1 = fmaxf(m1, mx1);
        float al0 = __expf(m0 - mn0), al1 = __expf(m1 - mn1);
        m0 = mn0; m1 = mn1;

        float rs0 = 0.0f, rs1 = 0.0f;
#pragma unroll
        for (int nt = 0; nt < 8; nt++) {
            s[nt][0] = __expf(s[nt][0] - mn0);
            s[nt][1] = __expf(s[nt][1] - mn0);
            s[nt][2] = __expf(s[nt][2] - mn1);
            s[nt][3] = __expf(s[nt][3] - mn1);
            rs0 += s[nt][0] + s[nt][1];
            rs1 += s[nt][2] + s[nt][3];
        }
        rs0 += __shfl_xor_sync(0xffffffffu, rs0, 1);
        rs0 += __shfl_xor_sync(0xffffffffu, rs0, 2);
        rs1 += __shfl_xor_sync(0xffffffffu, rs1, 1);
        rs1 += __shfl_xor_sync(0xffffffffu, rs1, 2);
        l0 = l0 * al0 + rs0;
        l1 = l1 * al1 + rs1;

#pragma unroll
        for (int nt = 0; nt < 8; nt++) {
            o[nt][0] *= al0; o[nt][1] *= al0;
            o[nt][2] *= al1; o[nt][3] *= al1;
        }

        // ---- O += P @ V : A-frag taken straight from s (permutation) ----
#pragma unroll
        for (int ks = 0; ks < 8; ks++) {
            unsigned a[4] = {f2tf(s[ks][0]), f2tf(s[ks][2]),
                             f2tf(s[ks][1]), f2tf(s[ks][3])};
#pragma unroll
            for (int nt = 0; nt < 8; nt++) {
                float2 bf = *(const float2*)
                    &sm[vbuf + (ks * 8 + nt) * 64 + ((lane ^ (nt << 2)) << 1)];
                unsigned bb[2] = {__float_as_uint(bf.x), __float_as_uint(bf.y)};
                mma_tf32(o[nt], a, bb);
            }
        }
    }

    // ---- epilogue ----
    float inv0 = 1.0f / l0, inv1 = 1.0f / l1;
    const int qa = q0 + w * 16 + g;
    const size_t rowA = ((size_t)(b * SEQ) + qa) * D_MODEL + h * DK;
    const size_t rowB = ((size_t)(b * SEQ) + qa + 8) * D_MODEL + h * DK;
#pragma unroll
    for (int nt = 0; nt < 8; nt++) {
        int c = nt * 8 + 2 * qg;
        *(float2*)&ctx[rowA + c] = make_float2(o[nt][0] * inv0, o[nt][1] * inv0);
        *(float2*)&ctx[rowB + c] = make_float2(o[nt][2] * inv1, o[nt][3] * inv1);
    }
#undef ATTN_ISSUE
}

// ---------------------------------------------------------------------------
// Launch
// ---------------------------------------------------------------------------
extern "C" void kernel_launch(void* const* d_in, const int* in_sizes, int n_in,
                              void* d_out, int out_size)
{
    const float* x  = (const float*)d_in[0];
    const float* Wq = (const float*)d_in[1];
    const float* bq = (const float*)d_in[2];
    const float* Wk = (const float*)d_in[3];
    const float* bk = (const float*)d_in[4];
    const float* Wv = (const float*)d_in[5];
    const float* bv = (const float*)d_in[6];
    const float* Wo = (const float*)d_in[7];
    const float* bo = (const float*)d_in[8];
    float* out = (float*)d_out;

    float *gq, *gkp, *gvp, *gctx, *gapk, *gwpk;
    cudaGetSymbolAddress((void**)&gq,   g_Q);
    cudaGetSymbolAddress((void**)&gkp,  g_Kp);
    cudaGetSymbolAddress((void**)&gvp,  g_Vp);
    cudaGetSymbolAddress((void**)&gctx, g_ctx);
    cudaGetSymbolAddress((void**)&gapk, g_Apk);
    cudaGetSymbolAddress((void**)&gwpk, g_Wpk);

    cudaFuncSetAttribute(attn_kernel,
                         cudaFuncAttributeMaxDynamicSharedMemorySize,
                         ATTN_SMEM_BYTES);

    const int WSZ = D_MODEL * D_MODEL;

    // pack weights + activations
    repack_W<<<576, 256>>>(Wq, gwpk + 0 * WSZ);
    repack_W<<<576, 256>>>(Wk, gwpk + 1 * WSZ);
    repack_W<<<576, 256>>>(Wv, gwpk + 2 * WSZ);
    repack_W<<<576, 256>>>(Wo, gwpk + 3 * WSZ);
    repack_A<<<6144, 256>>>(x, gapk);

    dim3 gg(NTILES, MTILES);   // (12, 128)
    mma_gemm<0><<<gg, 128>>>(gapk, gwpk + 0 * WSZ, bq, gq);
    mma_gemm<1><<<gg, 128>>>(gapk, gwpk + 1 * WSZ, bk, gkp);
    mma_gemm<2><<<gg, 128>>>(gapk, gwpk + 2 * WSZ, bv, gvp);

    dim3 ga(SEQ / 64, NHEAD, BATCH);   // (64, 12, 2)
    attn_kernel<<<ga, 128, ATTN_SMEM_BYTES>>>(gq, gkp, gvp, gctx);

    repack_A<<<6144, 256>>>(gctx, gapk);
    mma_gemm<3><<<gg, 128>>>(gapk, gwpk + 3 * WSZ, bo, out);
}

// round 5
// speedup vs baseline: 5.4031x; 1.6042x over previous
#include <cuda_runtime.h>
#include <cuda_fp16.h>

// ---------------------------------------------------------------------------
// MSA fp32: B=2, S=4096, D=768, H=12, dk=64 — all GEMMs on fp16 mma.sync
// (m16n8k16) with hi/lo split-fp16 for fp32-grade accuracy on inputs;
// P and V single fp16 (2^-11 rounding -> ~4e-4 ctx error, calibrated R4).
//   repack_A(x)      x -> hi/lo fp16 A-fragment tiles
//   repack_W x4      W -> hi/lo fp16 B-fragment tiles
//   mma_gemm<Q/K/V>  Q fp32 [B,H,S,64]; K hi/lo-packed frags; V fp16 frags
//   attn_kernel      flash attention, cp.async double-buffered, P in regs
//   repack_A(ctx); mma_gemm<OUT>
// ---------------------------------------------------------------------------

#define D_MODEL 768
#define NHEAD   12
#define DK      64
#define BATCH   2
#define SEQ     4096
#define MROWS   8192
#define KT16    48      // 768/16
#define NTILES  12
#define MTILES  128

__device__ float    g_Q  [BATCH * NHEAD * SEQ * DK];
__device__ unsigned g_Kp [BATCH * NHEAD * 64 * 4096];   // hi/lo packed words
__device__ unsigned g_Vp [BATCH * NHEAD * 64 * 2048];   // fp16 packed words
__device__ float    g_ctx[MROWS * D_MODEL];
__device__ unsigned g_Apk[(size_t)MROWS * D_MODEL];     // hi/lo A words
__device__ unsigned g_Wpk[4 * D_MODEL * D_MODEL];       // hi/lo B words x4

// ---------------------------------------------------------------------------
// helpers
// ---------------------------------------------------------------------------
// word: bits[15:0] = fp16(first/lower-k), bits[31:16] = fp16(second)
__device__ __forceinline__ unsigned pk(float first, float second) {
    unsigned r;
    asm("cvt.rn.f16x2.f32 %0, %1, %2;" : "=r"(r) : "f"(second), "f"(first));
    return r;
}
__device__ __forceinline__ void hsplit(float x, float& hi, float& lo) {
    hi = __half2float(__float2half_rn(x));   // rn: |lo| <= 2^-12 |x|
    lo = x - hi;                              // exact in fp32
}
__device__ __forceinline__ void mma_f16(float d[4], const unsigned a[4],
                                        const unsigned b[2]) {
    asm volatile(
        "mma.sync.aligned.m16n8k16.row.col.f32.f16.f16.f32 "
        "{%0,%1,%2,%3}, {%4,%5,%6,%7}, {%8,%9}, {%0,%1,%2,%3};"
        : "+f"(d[0]), "+f"(d[1]), "+f"(d[2]), "+f"(d[3])
        : "r"(a[0]), "r"(a[1]), "r"(a[2]), "r"(a[3]), "r"(b[0]), "r"(b[1]));
}
__device__ __forceinline__ void cp_async16(unsigned s_addr, const void* g_ptr) {
    asm volatile("cp.async.cg.shared.global [%0], [%1], 16;"
                 :: "r"(s_addr), "l"(g_ptr) : "memory");
}
__device__ __forceinline__ void cp_commit() {
    asm volatile("cp.async.commit_group;" ::: "memory");
}
__device__ __forceinline__ void cp_wait0() {
    asm volatile("cp.async.wait_group 0;" ::: "memory");
}

// ---------------------------------------------------------------------------
// repack_A: [8192,768] fp32 -> per-(64m x 16k) tile hi/lo A-frag words.
// Tile block = 1024 words: [hi 512][lo 512]; hi word addr within 512:
//   wq*128 + lane*4 + reg, lane=(q&7)*4+(p&3), reg=(q>>3)+2*(p>>2), p=k-pair.
// ---------------------------------------------------------------------------
__global__ void __launch_bounds__(256) repack_A(const float* __restrict__ A,
                                                unsigned* __restrict__ dst) {
    int idx = blockIdx.x * 256 + threadIdx.x;     // one float4 each
    int m  = idx / 192;
    int k4 = (idx % 192) * 4;
    float4 v = *(const float4*)&A[(size_t)m * D_MODEL + k4];
    float vv[4] = {v.x, v.y, v.z, v.w};
    int mtile = m >> 6, wq = (m & 63) >> 4, q = m & 15;
    int kt = k4 >> 4;
    size_t base = ((size_t)(mtile * KT16 + kt)) * 1024 + wq * 128;
#pragma unroll
    for (int pp = 0; pp < 2; pp++) {
        float h0, l0, h1, l1;
        hsplit(vv[2 * pp],     h0, l0);
        hsplit(vv[2 * pp + 1], h1, l1);
        int p = ((k4 & 15) >> 1) + pp;
        int reg = (q >> 3) + 2 * (p >> 2);
        int lane = (q & 7) * 4 + (p & 3);
        size_t a = base + lane * 4 + reg;
        dst[a]       = pk(h0, h1);
        dst[a + 512] = pk(l0, l1);
    }
}

// ---------------------------------------------------------------------------
// repack_W: [768,768] fp32 -> per-(16k x 64n) tile hi/lo B-frag words.
// Tile block = 1024 words [hi 512][lo 512]; hi addr: nb*64 + lane*2 + reg,
//   lane = (n&7)*4 + (p&3), reg = p>>2, p = (k&15)>>1.
// ---------------------------------------------------------------------------
__global__ void __launch_bounds__(256) repack_W(const float* __restrict__ W,
                                                unsigned* __restrict__ dst) {
    int idx = blockIdx.x * 256 + threadIdx.x;     // (k-pair, n-float4)
    int kp = idx / 192;
    int k  = kp * 2;
    int n4 = (idx % 192) * 4;
    float4 va = *(const float4*)&W[(size_t)k * D_MODEL + n4];
    float4 vb = *(const float4*)&W[(size_t)(k + 1) * D_MODEL + n4];
    float aa[4] = {va.x, va.y, va.z, va.w};
    float bb[4] = {vb.x, vb.y, vb.z, vb.w};
    int kt = k >> 4;
    int p = (k & 15) >> 1, reg = p >> 2, t = p & 3;
#pragma unroll
    for (int j = 0; j < 4; j++) {
        int n = n4 + j;
        int ntile = n >> 6, nb = (n & 63) >> 3, g = n & 7;
        size_t a = ((size_t)(kt * NTILES + ntile)) * 1024 +
                   nb * 64 + (g * 4 + t) * 2 + reg;
        float ah, al, bh, bl;
        hsplit(aa[j], ah, al);
        hsplit(bb[j], bh, bl);
        dst[a]       = pk(ah, bh);
        dst[a + 512] = pk(al, bl);
    }
}

// ---------------------------------------------------------------------------
// mma GEMM: C[8192,768] = A @ W + bias. CTA 64m x 64n, 4 warps, BK=32,
// double-buffered cp.async. MODE: 0=Q fp32, 1=K packed hi/lo, 2=V packed,
// 3=row-major fp32.
// ---------------------------------------------------------------------------
template <int MODE>
__global__ void __launch_bounds__(128) mma_gemm(
    const unsigned* __restrict__ Apk, const unsigned* __restrict__ Bpk,
    const float* __restrict__ bias, void* __restrict__ Cv)
{
    __shared__ unsigned As[2][2048];
    __shared__ unsigned Bs[2][2048];

    const int tid = threadIdx.x;
    const int lane = tid & 31;
    const int w = tid >> 5;
    const int g = lane >> 2;
    const int qg = lane & 3;
    const int ntile = blockIdx.x;
    const int mtile = blockIdx.y;

    float c[8][4];
#pragma unroll
    for (int nt = 0; nt < 8; nt++)
#pragma unroll
        for (int j = 0; j < 4; j++) c[nt][j] = 0.0f;

    unsigned sA[2] = {(unsigned)__cvta_generic_to_shared(&As[0][0]),
                      (unsigned)__cvta_generic_to_shared(&As[1][0])};
    unsigned sB[2] = {(unsigned)__cvta_generic_to_shared(&Bs[0][0]),
                      (unsigned)__cvta_generic_to_shared(&Bs[1][0])};

#define GEMM_ISSUE(IT)                                                        \
    do {                                                                      \
        int _b = (IT) & 1;                                                    \
        const uint4* _ga = (const uint4*)(Apk +                               \
            ((size_t)(mtile * KT16 + (IT) * 2)) * 1024);                      \
        cp_async16(sA[_b] + tid * 16,        _ga + tid);                      \
        cp_async16(sA[_b] + tid * 16 + 2048, _ga + 128 + tid);                \
        cp_async16(sA[_b] + tid * 16 + 4096, _ga + 256 + tid);                \
        cp_async16(sA[_b] + tid * 16 + 6144, _ga + 384 + tid);                \
        const uint4* _gb0 = (const uint4*)(Bpk +                              \
            ((size_t)((IT) * 2 * NTILES + ntile)) * 1024);                    \
        const uint4* _gb1 = (const uint4*)(Bpk +                              \
            ((size_t)(((IT) * 2 + 1) * NTILES + ntile)) * 1024);              \
        cp_async16(sB[_b] + tid * 16,        _gb0 + tid);                     \
        cp_async16(sB[_b] + tid * 16 + 2048, _gb0 + 128 + tid);               \
        cp_async16(sB[_b] + tid * 16 + 4096, _gb1 + tid);                     \
        cp_async16(sB[_b] + tid * 16 + 6144, _gb1 + 128 + tid);               \
        cp_commit();                                                          \
    } while (0)

    GEMM_ISSUE(0);

    for (int it = 0; it < 24; it++) {
        cp_wait0();
        __syncthreads();
        if (it + 1 < 24) GEMM_ISSUE(it + 1);
        const int buf = it & 1;
#pragma unroll
        for (int kt2 = 0; kt2 < 2; kt2++) {
            const unsigned* Ab = &As[buf][kt2 * 1024 + w * 128];
            uint4 ah4 = *(const uint4*)&Ab[lane * 4];
            uint4 al4 = *(const uint4*)&Ab[512 + lane * 4];
            unsigned ah[4] = {ah4.x, ah4.y, ah4.z, ah4.w};
            unsigned al[4] = {al4.x, al4.y, al4.z, al4.w};
            const unsigned* Bb = &Bs[buf][kt2 * 1024];
#pragma unroll
            for (int nt = 0; nt < 8; nt++) {
                uint2 bh2 = *(const uint2*)&Bb[nt * 64 + lane * 2];
                uint2 bl2 = *(const uint2*)&Bb[512 + nt * 64 + lane * 2];
                unsigned bh[2] = {bh2.x, bh2.y};
                unsigned bl[2] = {bl2.x, bl2.y};
                mma_f16(c[nt], ah, bh);
                mma_f16(c[nt], al, bh);
                mma_f16(c[nt], ah, bl);
            }
        }
        __syncthreads();
    }

    // ---- epilogue ----
    if (MODE == 0 || MODE == 3) {
        float* C = (float*)Cv;
#pragma unroll
        for (int nt = 0; nt < 8; nt++)
#pragma unroll
            for (int j = 0; j < 4; j++) {
                int m = mtile * 64 + w * 16 + g + ((j >= 2) ? 8 : 0);
                int n_local = nt * 8 + 2 * qg + (j & 1);
                float v = c[nt][j] + bias[ntile * 64 + n_local];
                if (MODE == 0) {
                    int b = m >> 12, s = m & 4095;
                    C[(size_t)(((b * NHEAD + ntile) << 12) + s) * DK + n_local] = v;
                } else {
                    C[(size_t)m * D_MODEL + ntile * 64 + n_local] = v;
                }
            }
    } else if (MODE == 1) {
        unsigned* C = (unsigned*)Cv;
        int b = mtile >> 6, keytile = mtile & 63;
        size_t base = ((size_t)(b * NHEAD + ntile) * 64 + keytile) * 4096;
#pragma unroll
        for (int nt = 0; nt < 8; nt++)
#pragma unroll
            for (int dlt = 0; dlt < 2; dlt++) {
                int klocal = w * 16 + g + 8 * dlt;
                float x = c[nt][2 * dlt]     + bias[ntile * 64 + nt * 8 + 2 * qg];
                float y = c[nt][2 * dlt + 1] + bias[ntile * 64 + nt * 8 + 2 * qg + 1];
                float xh, xl, yh, yl;
                hsplit(x, xh, xl);
                hsplit(y, yh, yl);
                size_t idx = (size_t)(((nt >> 1) * 8 + (klocal >> 3)) * 64 +
                             ((klocal & 7) * 4 + qg) * 2 + (nt & 1));
                C[base + idx]        = pk(xh, yh);
                C[base + 2048 + idx] = pk(xl, yl);
            }
    } else {   // MODE 2: V packed single fp16, pair adjacent keys via shfl
        unsigned* C = (unsigned*)Cv;
        int b = mtile >> 6, keytile = mtile & 63;
        size_t base = ((size_t)(b * NHEAD + ntile) * 64 + keytile) * 2048;
#pragma unroll
        for (int nt = 0; nt < 8; nt++)
#pragma unroll
            for (int dlt = 0; dlt < 2; dlt++)
#pragma unroll
                for (int j = 0; j < 2; j++) {
                    int d = nt * 8 + 2 * qg + j;
                    float x = c[nt][2 * dlt + j] + bias[ntile * 64 + d];
                    float y = __shfl_xor_sync(0xffffffffu, x, 4);
                    if (!(g & 1)) {
                        size_t idx = (size_t)((w * 8 + nt) * 64 +
                                     ((2 * qg + j) * 4 + (g >> 1)) * 2 + dlt);
                        C[base + idx] = pk(x, y);
                    }
                }
    }
#undef GEMM_ISSUE
}

// ---------------------------------------------------------------------------
// flash attention: 128 thr (4 warps), 64 q/CTA, 64 keys/iter, fp16 mma.
// Q hi/lo packed in prologue; K (hi/lo) and V (single) pre-packed, cp.async
// double-buffered. Score C-frag feeds PV A-frag directly (k16 layout match).
// smem (words): QHI 0, QLO 2048, K bufs 4096/8192 (hi|lo 2048 each),
// V bufs 12288/14336. Total 16384 words = 64KB.
// ---------------------------------------------------------------------------
#define W_QHI 0
#define W_QLO 2048
#define W_K0  4096
#define W_V0  12288
#define ATTN_SMEM_BYTES (16384 * 4)

__global__ void __launch_bounds__(128) attn_kernel(
    const float* __restrict__ Q, const unsigned* __restrict__ Kp,
    const unsigned* __restrict__ Vp, float* __restrict__ ctx)
{
    extern __shared__ unsigned smw[];
    const int tid  = threadIdx.x;
    const int lane = tid & 31;
    const int w    = tid >> 5;
    const int g    = lane >> 2;
    const int qg   = lane & 3;

    const int q0 = blockIdx.x * 64;
    const int h  = blockIdx.y;
    const int b  = blockIdx.z;
    const float*    Qb = Q  + (size_t)(b * NHEAD + h) * SEQ * DK;
    const unsigned* Kh = Kp + (size_t)(b * NHEAD + h) * 64 * 4096;
    const unsigned* Vh = Vp + (size_t)(b * NHEAD + h) * 64 * 2048;

    unsigned smK = (unsigned)__cvta_generic_to_shared(smw) + W_K0 * 4;
    unsigned smV = (unsigned)__cvta_generic_to_shared(smw) + W_V0 * 4;

#define ATTN_ISSUE(KT)                                                        \
    do {                                                                      \
        int _b2 = (KT) & 1;                                                   \
        const uint4* _gk = (const uint4*)(Kh + (size_t)(KT) * 4096);          \
        const uint4* _gv = (const uint4*)(Vh + (size_t)(KT) * 2048);          \
        unsigned _sk = smK + _b2 * 16384;                                     \
        unsigned _sv = smV + _b2 * 8192;                                      \
        _Pragma("unroll")                                                     \
        for (int _i = 0; _i < 8; _i++)                                        \
            cp_async16(_sk + (_i * 128 + tid) * 16, _gk + _i * 128 + tid);    \
        _Pragma("unroll")                                                     \
        for (int _i = 0; _i < 4; _i++)                                        \
            cp_async16(_sv + (_i * 128 + tid) * 16, _gv + _i * 128 + tid);    \
        cp_commit();                                                          \
    } while (0)

    // ---- pack Q (hi/lo fp16, scaled 1/8) ----
#pragma unroll
    for (int i = 0; i < 8; i++) {
        int idx = i * 128 + tid;
        int q  = idx >> 4;
        int d0 = (idx & 15) * 4;
        float4 v = *(const float4*)&Qb[(size_t)(q0 + q) * DK + d0];
        float vv[4] = {v.x * 0.125f, v.y * 0.125f, v.z * 0.125f, v.w * 0.125f};
        int wq = q >> 4, qr = q & 15, ks = d0 >> 4;
        int base = (wq * 4 + ks) * 128;
#pragma unroll
        for (int pp = 0; pp < 2; pp++) {
            float h0, l0, h1, l1;
            hsplit(vv[2 * pp],     h0, l0);
            hsplit(vv[2 * pp + 1], h1, l1);
            int p = ((d0 & 15) >> 1) + pp;
            int reg = (qr >> 3) + 2 * (p >> 2);
            int ln = (qr & 7) * 4 + (p & 3);
            int a = base + ln * 4 + reg;
            smw[W_QHI + a] = pk(h0, h1);
            smw[W_QLO + a] = pk(l0, l1);
        }
    }

    ATTN_ISSUE(0);

    float m0 = -1e30f, m1 = -1e30f, l0 = 0.0f, l1 = 0.0f;
    float o[8][4];
#pragma unroll
    for (int nt = 0; nt < 8; nt++)
#pragma unroll
        for (int j = 0; j < 4; j++) o[nt][j] = 0.0f;

    for (int kt = 0; kt < SEQ / 64; kt++) {
        cp_wait0();
        __syncthreads();
        if (kt + 1 < SEQ / 64) ATTN_ISSUE(kt + 1);

        const int kbuf = W_K0 + (kt & 1) * 4096;
        const int vbuf = W_V0 + (kt & 1) * 2048;

        // ---- scores: 3-mma split-fp16 ----
        float s[8][4];
#pragma unroll
        for (int nt = 0; nt < 8; nt++)
#pragma unroll
            for (int j = 0; j < 4; j++) s[nt][j] = 0.0f;

#pragma unroll
        for (int ks = 0; ks < 4; ks++) {
            uint4 ah4 = *(const uint4*)&smw[W_QHI + (w * 4 + ks) * 128 + lane * 4];
            uint4 al4 = *(const uint4*)&smw[W_QLO + (w * 4 + ks) * 128 + lane * 4];
            unsigned ah[4] = {ah4.x, ah4.y, ah4.z, ah4.w};
            unsigned al[4] = {al4.x, al4.y, al4.z, al4.w};
#pragma unroll
            for (int nt = 0; nt < 8; nt++) {
                uint2 bh2 = *(const uint2*)&smw[kbuf + (ks * 8 + nt) * 64 + lane * 2];
                uint2 bl2 = *(const uint2*)&smw[kbuf + 2048 + (ks * 8 + nt) * 64 + lane * 2];
                unsigned bh[2] = {bh2.x, bh2.y};
                unsigned bl[2] = {bl2.x, bl2.y};
                mma_f16(s[nt], ah, bh);
                mma_f16(s[nt], al, bh);
                mma_f16(s[nt], ah, bl);
            }
        }

        // ---- online softmax (registers + quad shuffles) ----
        float mx0 = -1e30f, mx1 = -1e30f;
#pragma unroll
        for (int nt = 0; nt < 8; nt++) {
            mx0 = fmaxf(mx0, fmaxf(s[nt][0], s[nt][1]));
            mx1 = fmaxf(mx1, fmaxf(s[nt][2], s[nt][3]));
        }
        mx0 = fmaxf(mx0, __shfl_xor_sync(0xffffffffu, mx0, 1));
        mx0 = fmaxf(mx0, __shfl_xor_sync(0xffffffffu, mx0, 2));
        mx1 = fmaxf(mx1, __shfl_xor_sync(0xffffffffu, mx1, 1));
        mx1 = fmaxf(mx1, __shfl_xor_sync(0xffffffffu, mx1, 2));

        float mn0 = fmaxf(m0, mx0), mn1 = fmaxf(m1, mx1);
        float al0 = __expf(m0 - mn0), al1 = __expf(m1 - mn1);
        m0 = mn0; m1 = mn1;

        float rs0 = 0.0f, rs1 = 0.0f;
#pragma unroll
        for (int nt = 0; nt < 8; nt++) {
            s[nt][0] = __expf(s[nt][0] - mn0);
            s[nt][1] = __expf(s[nt][1] - mn0);
            s[nt][2] = __expf(s[nt][2] - mn1);
            s[nt][3] = __expf(s[nt][3] - mn1);
            rs0 += s[nt][0] + s[nt][1];
            rs1 += s[nt][2] + s[nt][3];
        }
        rs0 += __shfl_xor_sync(0xffffffffu, rs0, 1);
        rs0 += __shfl_xor_sync(0xffffffffu, rs0, 2);
        rs1 += __shfl_xor_sync(0xffffffffu, rs1, 1);
        rs1 += __shfl_xor_sync(0xffffffffu, rs1, 2);
        l0 = l0 * al0 + rs0;
        l1 = l1 * al1 + rs1;

#pragma unroll
        for (int nt = 0; nt < 8; nt++) {
            o[nt][0] *= al0; o[nt][1] *= al0;
            o[nt][2] *= al1; o[nt][3] *= al1;
        }

        // ---- O += P @ V : C-frag -> A-frag directly (k16 layout match) ----
#pragma unroll
        for (int ksv = 0; ksv < 4; ksv++) {
            unsigned a[4] = {pk(s[2 * ksv][0],     s[2 * ksv][1]),
                             pk(s[2 * ksv][2],     s[2 * ksv][3]),
                             pk(s[2 * ksv + 1][0], s[2 * ksv + 1][1]),
                             pk(s[2 * ksv + 1][2], s[2 * ksv + 1][3])};
#pragma unroll
            for (int nt = 0; nt < 8; nt++) {
                uint2 bv2 = *(const uint2*)&smw[vbuf + (ksv * 8 + nt) * 64 + lane * 2];
                unsigned bv[2] = {bv2.x, bv2.y};
                mma_f16(o[nt], a, bv);
            }
        }
    }

    // ---- epilogue ----
    float inv0 = 1.0f / l0, inv1 = 1.0f / l1;
    const int qa = q0 + w * 16 + g;
    const size_t rowA = ((size_t)(b * SEQ) + qa) * D_MODEL + h * DK;
    const size_t rowB = ((size_t)(b * SEQ) + qa + 8) * D_MODEL + h * DK;
#pragma unroll
    for (int nt = 0; nt < 8; nt++) {
        int cc = nt * 8 + 2 * qg;
        *(float2*)&ctx[rowA + cc] = make_float2(o[nt][0] * inv0, o[nt][1] * inv0);
        *(float2*)&ctx[rowB + cc] = make_float2(o[nt][2] * inv1, o[nt][3] * inv1);
    }
#undef ATTN_ISSUE
}

// ---------------------------------------------------------------------------
// Launch
// ---------------------------------------------------------------------------
extern "C" void kernel_launch(void* const* d_in, const int* in_sizes, int n_in,
                              void* d_out, int out_size)
{
    const float* x  = (const float*)d_in[0];
    const float* Wq = (const float*)d_in[1];
    const float* bq = (const float*)d_in[2];
    const float* Wk = (const float*)d_in[3];
    const float* bk = (const float*)d_in[4];
    const float* Wv = (const float*)d_in[5];
    const float* bv = (const float*)d_in[6];
    const float* Wo = (const float*)d_in[7];
    const float* bo = (const float*)d_in[8];
    float* out = (float*)d_out;

    float *gq, *gctx;
    unsigned *gkp, *gvp, *gapk, *gwpk;
    cudaGetSymbolAddress((void**)&gq,   g_Q);
    cudaGetSymbolAddress((void**)&gkp,  g_Kp);
    cudaGetSymbolAddress((void**)&gvp,  g_Vp);
    cudaGetSymbolAddress((void**)&gctx, g_ctx);
    cudaGetSymbolAddress((void**)&gapk, g_Apk);
    cudaGetSymbolAddress((void**)&gwpk, g_Wpk);

    cudaFuncSetAttribute(attn_kernel,
                         cudaFuncAttributeMaxDynamicSharedMemorySize,
                         ATTN_SMEM_BYTES);

    const int WSZ = D_MODEL * D_MODEL;

    repack_W<<<288, 256>>>(Wq, gwpk + 0 * WSZ);
    repack_W<<<288, 256>>>(Wk, gwpk + 1 * WSZ);
    repack_W<<<288, 256>>>(Wv, gwpk + 2 * WSZ);
    repack_W<<<288, 256>>>(Wo, gwpk + 3 * WSZ);
    repack_A<<<6144, 256>>>(x, gapk);

    dim3 gg(NTILES, MTILES);   // (12, 128)
    mma_gemm<0><<<gg, 128>>>(gapk, gwpk + 0 * WSZ, bq, gq);
    mma_gemm<1><<<gg, 128>>>(gapk, gwpk + 1 * WSZ, bk, gkp);
    mma_gemm<2><<<gg, 128>>>(gapk, gwpk + 2 * WSZ, bv, gvp);

    dim3 ga(SEQ / 64, NHEAD, BATCH);   // (64, 12, 2)
    attn_kernel<<<ga, 128, ATTN_SMEM_BYTES>>>(gq, gkp, gvp, gctx);

    repack_A<<<6144, 256>>>(gctx, gapk);
    mma_gemm<3><<<gg, 128>>>(gapk, gwpk + 3 * WSZ, bo, out);
}

// round 8
// speedup vs baseline: 6.7503x; 1.2493x over previous
#include <cuda_runtime.h>
#include <cuda_fp16.h>
#include <cstdint>
#include <cstddef>

// ---------------------------------------------------------------------------
// MSA fp32: B=2, S=4096, D=768, H=12, dk=64 — fp16 mma.sync (m16n8k16).
// Accuracy scheme (calibrated R4/R5): A-side hi/lo split compensated,
// W and K single fp16 (predicted rel_err ~3.5e-4 < 1e-3).
//   repack_A(x)      x -> hi/lo fp16 A-fragment tiles
//   repack_W x4      W -> single fp16 B-fragment tiles
//   mma_gemm<Q/K/V>  Q fp32 [B,H,S,64]; K fp16 frags; V fp16 frags
//   attn_kernel      flash attention, 128q/CTA, 8 warps, P in regs
//   repack_A(ctx); mma_gemm<OUT>
// ---------------------------------------------------------------------------

#define D_MODEL 768
#define NHEAD   12
#define DK      64
#define BATCH   2
#define SEQ     4096
#define MROWS   8192
#define KT16    48      // 768/16
#define NTILES  12
#define MTILES  128

__device__ float    g_Q  [BATCH * NHEAD * SEQ * DK];
__device__ unsigned g_Kp [BATCH * NHEAD * 64 * 2048];   // fp16 packed words
__device__ unsigned g_Vp [BATCH * NHEAD * 64 * 2048];   // fp16 packed words
__device__ float    g_ctx[MROWS * D_MODEL];
__device__ unsigned g_Apk[(size_t)MROWS * D_MODEL];     // hi/lo A words
__device__ unsigned g_Wpk[4 * D_MODEL * D_MODEL / 2];   // fp16 B words x4

// ---------------------------------------------------------------------------
// helpers
// ---------------------------------------------------------------------------
__device__ __forceinline__ unsigned pk(float first, float second) {
    unsigned r;
    asm("cvt.rn.f16x2.f32 %0, %1, %2;" : "=r"(r) : "f"(second), "f"(first));
    return r;
}
__device__ __forceinline__ void hsplit(float x, float& hi, float& lo) {
    hi = __half2float(__float2half_rn(x));
    lo = x - hi;
}
__device__ __forceinline__ void mma_f16(float d[4], const unsigned a[4],
                                        const unsigned b[2]) {
    asm volatile(
        "mma.sync.aligned.m16n8k16.row.col.f32.f16.f16.f32 "
        "{%0,%1,%2,%3}, {%4,%5,%6,%7}, {%8,%9}, {%0,%1,%2,%3};"
        : "+f"(d[0]), "+f"(d[1]), "+f"(d[2]), "+f"(d[3])
        : "r"(a[0]), "r"(a[1]), "r"(a[2]), "r"(a[3]), "r"(b[0]), "r"(b[1]));
}
__device__ __forceinline__ void cp_async16(unsigned s_addr, const void* g_ptr) {
    asm volatile("cp.async.cg.shared.global [%0], [%1], 16;"
                 :: "r"(s_addr), "l"(g_ptr) : "memory");
}
__device__ __forceinline__ void cp_commit() {
    asm volatile("cp.async.commit_group;" ::: "memory");
}
__device__ __forceinline__ void cp_wait0() {
    asm volatile("cp.async.wait_group 0;" ::: "memory");
}
__device__ __forceinline__ unsigned smem_u32(const void* p) {
    unsigned a;
    asm("{ .reg .u64 t; cvta.to.shared.u64 t, %1; cvt.u32.u64 %0, t; }"
        : "=r"(a) : "l"(p));
    return a;
}

// ---------------------------------------------------------------------------
// repack_A: [8192,768] fp32 -> per-(64m x 16k) tile hi/lo A-frag words.
// Tile block = 1024 words: [hi 512][lo 512]; hi word addr within 512:
//   wq*128 + lane*4 + reg, lane=(q&7)*4+(p&3), reg=(q>>3)+2*(p>>2), p=k-pair.
// ---------------------------------------------------------------------------
__global__ void __launch_bounds__(256) repack_A(const float* __restrict__ A,
                                                unsigned* __restrict__ dst) {
    int idx = blockIdx.x * 256 + threadIdx.x;     // one float4 each
    int m  = idx / 192;
    int k4 = (idx % 192) * 4;
    float4 v = *(const float4*)&A[(size_t)m * D_MODEL + k4];
    float vv[4] = {v.x, v.y, v.z, v.w};
    int mtile = m >> 6, wq = (m & 63) >> 4, q = m & 15;
    int kt = k4 >> 4;
    size_t base = ((size_t)(mtile * KT16 + kt)) * 1024 + wq * 128;
#pragma unroll
    for (int pp = 0; pp < 2; pp++) {
        float h0, l0, h1, l1;
        hsplit(vv[2 * pp],     h0, l0);
        hsplit(vv[2 * pp + 1], h1, l1);
        int p = ((k4 & 15) >> 1) + pp;
        int reg = (q >> 3) + 2 * (p >> 2);
        int lane = (q & 7) * 4 + (p & 3);
        size_t a = base + lane * 4 + reg;
        dst[a]       = pk(h0, h1);
        dst[a + 512] = pk(l0, l1);
    }
}

// ---------------------------------------------------------------------------
// repack_W: [768,768] fp32 -> per-(16k x 64n) tile SINGLE fp16 B-frag words.
// Tile block = 512 words; addr: nb*64 + lane*2 + reg,
//   lane = (n&7)*4 + (p&3), reg = p>>2, p = (k&15)>>1.
// ---------------------------------------------------------------------------
__global__ void __launch_bounds__(256) repack_W(const float* __restrict__ W,
                                                unsigned* __restrict__ dst) {
    int idx = blockIdx.x * 256 + threadIdx.x;     // (k-pair, n-float4)
    int kp = idx / 192;
    int k  = kp * 2;
    int n4 = (idx % 192) * 4;
    float4 va = *(const float4*)&W[(size_t)k * D_MODEL + n4];
    float4 vb = *(const float4*)&W[(size_t)(k + 1) * D_MODEL + n4];
    float aa[4] = {va.x, va.y, va.z, va.w};
    float bb[4] = {vb.x, vb.y, vb.z, vb.w};
    int kt = k >> 4;
    int p = (k & 15) >> 1, reg = p >> 2, t = p & 3;
#pragma unroll
    for (int j = 0; j < 4; j++) {
        int n = n4 + j;
        int ntile = n >> 6, nb = (n & 63) >> 3, g = n & 7;
        size_t a = ((size_t)(kt * NTILES + ntile)) * 512 +
                   nb * 64 + (g * 4 + t) * 2 + reg;
        dst[a] = pk(aa[j], bb[j]);
    }
}

// ---------------------------------------------------------------------------
// mma GEMM: C[8192,768] = A @ W + bias. CTA 64m x 64n, 4 warps, BK=32,
// double-buffered cp.async. 2 mma streams (A hi/lo x W fp16).
// MODE: 0=Q fp32, 1=K packed fp16, 2=V packed fp16, 3=row-major fp32.
// ---------------------------------------------------------------------------
template <int MODE>
__global__ void __launch_bounds__(128) mma_gemm(
    const unsigned* __restrict__ Apk, const unsigned* __restrict__ Bpk,
    const float* __restrict__ bias, void* __restrict__ Cv)
{
    __shared__ unsigned As[2][2048];
    __shared__ unsigned Bs[2][1024];

    const int tid = threadIdx.x;
    const int lane = tid & 31;
    const int w = tid >> 5;
    const int g = lane >> 2;
    const int qg = lane & 3;
    const int ntile = blockIdx.x;
    const int mtile = blockIdx.y;

    float c[8][4];
#pragma unroll
    for (int nt = 0; nt < 8; nt++)
#pragma unroll
        for (int j = 0; j < 4; j++) c[nt][j] = 0.0f;

    unsigned sA[2] = {smem_u32(&As[0][0]), smem_u32(&As[1][0])};
    unsigned sB[2] = {smem_u32(&Bs[0][0]), smem_u32(&Bs[1][0])};

#define GEMM_ISSUE(IT)                                                        \
    do {                                                                      \
        int _b = (IT) & 1;                                                    \
        const uint4* _ga = (const uint4*)(Apk +                               \
            ((size_t)(mtile * KT16 + (IT) * 2)) * 1024);                      \
        cp_async16(sA[_b] + tid * 16,        _ga + tid);                      \
        cp_async16(sA[_b] + tid * 16 + 2048, _ga + 128 + tid);                \
        cp_async16(sA[_b] + tid * 16 + 4096, _ga + 256 + tid);                \
        cp_async16(sA[_b] + tid * 16 + 6144, _ga + 384 + tid);                \
        const uint4* _gb0 = (const uint4*)(Bpk +                              \
            ((size_t)((IT) * 2 * NTILES + ntile)) * 512);                     \
        const uint4* _gb1 = (const uint4*)(Bpk +                              \
            ((size_t)(((IT) * 2 + 1) * NTILES + ntile)) * 512);               \
        cp_async16(sB[_b] + tid * 16,        _gb0 + tid);                     \
        cp_async16(sB[_b] + tid * 16 + 2048, _gb1 + tid);                     \
        cp_commit();                                                          \
    } while (0)

    GEMM_ISSUE(0);

    for (int it = 0; it < 24; it++) {
        cp_wait0();
        __syncthreads();
        if (it + 1 < 24) GEMM_ISSUE(it + 1);
        const int buf = it & 1;
#pragma unroll
        for (int kt2 = 0; kt2 < 2; kt2++) {
            const unsigned* Ab = &As[buf][kt2 * 1024 + w * 128];
            uint4 ah4 = *(const uint4*)&Ab[lane * 4];
            uint4 al4 = *(const uint4*)&Ab[512 + lane * 4];
            unsigned ah[4] = {ah4.x, ah4.y, ah4.z, ah4.w};
            unsigned al[4] = {al4.x, al4.y, al4.z, al4.w};
            const unsigned* Bb = &Bs[buf][kt2 * 512];
#pragma unroll
            for (int nt = 0; nt < 8; nt++) {
                uint2 bh2 = *(const uint2*)&Bb[nt * 64 + lane * 2];
                unsigned bh[2] = {bh2.x, bh2.y};
                mma_f16(c[nt], ah, bh);
                mma_f16(c[nt], al, bh);
            }
        }
        __syncthreads();
    }

    // ---- epilogue ----
    if (MODE == 0 || MODE == 3) {
        float* C = (float*)Cv;
#pragma unroll
        for (int nt = 0; nt < 8; nt++)
#pragma unroll
            for (int j = 0; j < 4; j++) {
                int m = mtile * 64 + w * 16 + g + ((j >= 2) ? 8 : 0);
                int n_local = nt * 8 + 2 * qg + (j & 1);
                float v = c[nt][j] + bias[ntile * 64 + n_local];
                if (MODE == 0) {
                    int b = m >> 12, s = m & 4095;
                    C[(size_t)(((b * NHEAD + ntile) << 12) + s) * DK + n_local] = v;
                } else {
                    C[(size_t)m * D_MODEL + ntile * 64 + n_local] = v;
                }
            }
    } else if (MODE == 1) {
        unsigned* C = (unsigned*)Cv;
        int b = mtile >> 6, keytile = mtile & 63;
        size_t base = ((size_t)(b * NHEAD + ntile) * 64 + keytile) * 2048;
#pragma unroll
        for (int nt = 0; nt < 8; nt++)
#pragma unroll
            for (int dlt = 0; dlt < 2; dlt++) {
                int klocal = w * 16 + g + 8 * dlt;
                float x = c[nt][2 * dlt]     + bias[ntile * 64 + nt * 8 + 2 * qg];
                float y = c[nt][2 * dlt + 1] + bias[ntile * 64 + nt * 8 + 2 * qg + 1];
                size_t idx = (size_t)(((nt >> 1) * 8 + (klocal >> 3)) * 64 +
                             ((klocal & 7) * 4 + qg) * 2 + (nt & 1));
                C[base + idx] = pk(x, y);
            }
    } else {   // MODE 2: V packed single fp16, pair adjacent keys via shfl
        unsigned* C = (unsigned*)Cv;
        int b = mtile >> 6, keytile = mtile & 63;
        size_t base = ((size_t)(b * NHEAD + ntile) * 64 + keytile) * 2048;
#pragma unroll
        for (int nt = 0; nt < 8; nt++)
#pragma unroll
            for (int dlt = 0; dlt < 2; dlt++)
#pragma unroll
                for (int j = 0; j < 2; j++) {
                    int d = nt * 8 + 2 * qg + j;
                    float x = c[nt][2 * dlt + j] + bias[ntile * 64 + d];
                    float y = __shfl_xor_sync(0xffffffffu, x, 4);
                    if (!(g & 1)) {
                        size_t idx = (size_t)((w * 8 + nt) * 64 +
                                     ((2 * qg + j) * 4 + (g >> 1)) * 2 + dlt);
                        C[base + idx] = pk(x, y);
                    }
                }
    }
#undef GEMM_ISSUE
}

// ---------------------------------------------------------------------------
// flash attention: 256 thr (8 warps), 128 q/CTA, 64 keys/iter, fp16 mma.
// Q hi/lo packed in prologue; K (fp16) and V (fp16) pre-packed, cp.async
// double-buffered. Scores 2-mma (Qhi/Qlo x Kfp16); C-frag feeds PV A-frag.
// smem (words): QHI 0, QLO 4096, K bufs 8192/10240, V bufs 12288/14336.
// Total 16384 words = 64KB.
// ---------------------------------------------------------------------------
#define W_QHI 0
#define W_QLO 4096
#define W_K0  8192
#define W_V0  12288
#define ATTN_SMEM_BYTES (16384 * 4)

__global__ void __launch_bounds__(256) attn_kernel(
    const float* __restrict__ Q, const unsigned* __restrict__ Kp,
    const unsigned* __restrict__ Vp, float* __restrict__ ctx)
{
    extern __shared__ unsigned smw[];
    const int tid  = threadIdx.x;
    const int lane = tid & 31;
    const int w    = tid >> 5;    // 0..7
    const int g    = lane >> 2;
    const int qg   = lane & 3;

    const int q0 = blockIdx.x * 128;
    const int h  = blockIdx.y;
    const int b  = blockIdx.z;
    const float*    Qb = Q  + (size_t)(b * NHEAD + h) * SEQ * DK;
    const unsigned* Kh = Kp + (size_t)(b * NHEAD + h) * 64 * 2048;
    const unsigned* Vh = Vp + (size_t)(b * NHEAD + h) * 64 * 2048;

    unsigned smK = smem_u32(smw) + W_K0 * 4;
    unsigned smV = smem_u32(smw) + W_V0 * 4;

#define ATTN_ISSUE(KT)                                                        \
    do {                                                                      \
        int _b2 = (KT) & 1;                                                   \
        const uint4* _gk = (const uint4*)(Kh + (size_t)(KT) * 2048);          \
        const uint4* _gv = (const uint4*)(Vh + (size_t)(KT) * 2048);          \
        unsigned _sk = smK + _b2 * 8192;                                      \
        unsigned _sv = smV + _b2 * 8192;                                      \
        _Pragma("unroll")                                                     \
        for (int _i = 0; _i < 2; _i++)                                        \
            cp_async16(_sk + (_i * 256 + tid) * 16, _gk + _i * 256 + tid);    \
        _Pragma("unroll")                                                     \
        for (int _i = 0; _i < 2; _i++)                                        \
            cp_async16(_sv + (_i * 256 + tid) * 16, _gv + _i * 256 + tid);    \
        cp_commit();                                                          \
    } while (0)

    // ---- pack Q (hi/lo fp16, scaled 1/8): 128 rows ----
#pragma unroll
    for (int i = 0; i < 8; i++) {
        int idx = i * 256 + tid;
        int q  = idx >> 4;              // 0..127
        int d0 = (idx & 15) * 4;
        float4 v = *(const float4*)&Qb[(size_t)(q0 + q) * DK + d0];
        float vv[4] = {v.x * 0.125f, v.y * 0.125f, v.z * 0.125f, v.w * 0.125f};
        int wq = q >> 4, qr = q & 15, ks = d0 >> 4;
        int base = (wq * 4 + ks) * 128;
#pragma unroll
        for (int pp = 0; pp < 2; pp++) {
            float h0, l0, h1, l1;
            hsplit(vv[2 * pp],     h0, l0);
            hsplit(vv[2 * pp + 1], h1, l1);
            int p = ((d0 & 15) >> 1) + pp;
            int reg = (qr >> 3) + 2 * (p >> 2);
            int ln = (qr & 7) * 4 + (p & 3);
            int a = base + ln * 4 + reg;
            smw[W_QHI + a] = pk(h0, h1);
            smw[W_QLO + a] = pk(l0, l1);
        }
    }

    ATTN_ISSUE(0);

    float m0 = -1e30f, m1 = -1e30f, l0 = 0.0f, l1 = 0.0f;
    float o[8][4];
#pragma unroll
    for (int nt = 0; nt < 8; nt++)
#pragma unroll
        for (int j = 0; j < 4; j++) o[nt][j] = 0.0f;

    for (int kt = 0; kt < SEQ / 64; kt++) {
        cp_wait0();
        __syncthreads();
        if (kt + 1 < SEQ / 64) ATTN_ISSUE(kt + 1);

        const int kbuf = W_K0 + (kt & 1) * 2048;
        const int vbuf = W_V0 + (kt & 1) * 2048;

        // ---- scores: 2-mma (Q hi + Q lo) x K fp16 ----
        float s[8][4];
#pragma unroll
        for (int nt = 0; nt < 8; nt++)
#pragma unroll
            for (int j = 0; j < 4; j++) s[nt][j] = 0.0f;

#pragma unroll
        for (int ks = 0; ks < 4; ks++) {
            uint4 ah4 = *(const uint4*)&smw[W_QHI + (w * 4 + ks) * 128 + lane * 4];
            uint4 al4 = *(const uint4*)&smw[W_QLO + (w * 4 + ks) * 128 + lane * 4];
            unsigned ah[4] = {ah4.x, ah4.y, ah4.z, ah4.w};
            unsigned al[4] = {al4.x, al4.y, al4.z, al4.w};
#pragma unroll
            for (int nt = 0; nt < 8; nt++) {
                uint2 bh2 = *(const uint2*)&smw[kbuf + (ks * 8 + nt) * 64 + lane * 2];
                unsigned bh[2] = {bh2.x, bh2.y};
                mma_f16(s[nt], ah, bh);
                mma_f16(s[nt], al, bh);
            }
        }

        // ---- online softmax (registers + quad shuffles) ----
        float mx0 = -1e30f, mx1 = -1e30f;
#pragma unroll
        for (int nt = 0; nt < 8; nt++) {
            mx0 = fmaxf(mx0, fmaxf(s[nt][0], s[nt][1]));
            mx1 = fmaxf(mx1, fmaxf(s[nt][2], s[nt][3]));
        }
        mx0 = fmaxf(mx0, __shfl_xor_sync(0xffffffffu, mx0, 1));
        mx0 = fmaxf(mx0, __shfl_xor_sync(0xffffffffu, mx0, 2));
        mx1 = fmaxf(mx1, __shfl_xor_sync(0xffffffffu, mx1, 1));
        mx1 = fmaxf(mx1, __shfl_xor_sync(0xffffffffu, mx1, 2));

        float mn0 = fmaxf(m0, mx0), mn1 = fmaxf(m1, mx1);
        float al0 = __expf(m0 - mn0), al1 = __expf(m1 - mn1);
        m0 = mn0; m1 = mn1;

        float rs0 = 0.0f, rs1 = 0.0f;
#pragma unroll
        for (int nt = 0; nt < 8; nt++) {
            s[nt][0] = __expf(s[nt][0] - mn0);
            s[nt][1] = __expf(s[nt][1] - mn0);
            s[nt][2] = __expf(s[nt][2] - mn1);
            s[nt][3] = __expf(s[nt][3] - mn1);
            rs0 += s[nt][0] + s[nt][1];
            rs1 += s[nt][2] + s[nt][3];
        }
        rs0 += __shfl_xor_sync(0xffffffffu, rs0, 1);
        rs0 += __shfl_xor_sync(0xffffffffu, rs0, 2);
        rs1 += __shfl_xor_sync(0xffffffffu, rs1, 1);
        rs1 += __shfl_xor_sync(0xffffffffu, rs1, 2);
        l0 = l0 * al0 + rs0;
        l1 = l1 * al1 + rs1;

#pragma unroll
        for (int nt = 0; nt < 8; nt++) {
            o[nt][0] *= al0; o[nt][1] *= al0;
            o[nt][2] *= al1; o[nt][3] *= al1;
        }

        // ---- O += P @ V : C-frag -> A-frag directly (k16 layout match) ----
#pragma unroll
        for (int ksv = 0; ksv < 4; ksv++) {
            unsigned a[4] = {pk(s[2 * ksv][0],     s[2 * ksv][1]),
                             pk(s[2 * ksv][2],     s[2 * ksv][3]),
                             pk(s[2 * ksv + 1][0], s[2 * ksv + 1][1]),
                             pk(s[2 * ksv + 1][2], s[2 * ksv + 1][3])};
#pragma unroll
            for (int nt = 0; nt < 8; nt++) {
                uint2 bv2 = *(const uint2*)&smw[vbuf + (ksv * 8 + nt) * 64 + lane * 2];
                unsigned bv[2] = {bv2.x, bv2.y};
                mma_f16(o[nt], a, bv);
            }
        }
    }

    // ---- epilogue ----
    float inv0 = 1.0f / l0, inv1 = 1.0f / l1;
    const int qa = q0 + w * 16 + g;
    const size_t rowA = ((size_t)(b * SEQ) + qa) * D_MODEL + h * DK;
    const size_t rowB = ((size_t)(b * SEQ) + qa + 8) * D_MODEL + h * DK;
#pragma unroll
    for (int nt = 0; nt < 8; nt++) {
        int cc = nt * 8 + 2 * qg;
        *(float2*)&ctx[rowA + cc] = make_float2(o[nt][0] * inv0, o[nt][1] * inv0);
        *(float2*)&ctx[rowB + cc] = make_float2(o[nt][2] * inv1, o[nt][3] * inv1);
    }
#undef ATTN_ISSUE
}

// ---------------------------------------------------------------------------
// Launch
// ---------------------------------------------------------------------------
extern "C" void kernel_launch(void* const* d_in, const int* in_sizes, int n_in,
                              void* d_out, int out_size)
{
    const float* x  = (const float*)d_in[0];
    const float* Wq = (const float*)d_in[1];
    const float* bq = (const float*)d_in[2];
    const float* Wk = (const float*)d_in[3];
    const float* bk = (const float*)d_in[4];
    const float* Wv = (const float*)d_in[5];
    const float* bv = (const float*)d_in[6];
    const float* Wo = (const float*)d_in[7];
    const float* bo = (const float*)d_in[8];
    float* out = (float*)d_out;

    float *gq, *gctx;
    unsigned *gkp, *gvp, *gapk, *gwpk;
    cudaGetSymbolAddress((void**)&gq,   g_Q);
    cudaGetSymbolAddress((void**)&gkp,  g_Kp);
    cudaGetSymbolAddress((void**)&gvp,  g_Vp);
    cudaGetSymbolAddress((void**)&gctx, g_ctx);
    cudaGetSymbolAddress((void**)&gapk, g_Apk);
    cudaGetSymbolAddress((void**)&gwpk, g_Wpk);

    cudaFuncSetAttribute(attn_kernel,
                         cudaFuncAttributeMaxDynamicSharedMemorySize,
                         ATTN_SMEM_BYTES);

    const size_t WSZ = (size_t)D_MODEL * D_MODEL / 2;   // words per packed W

    repack_W<<<288, 256>>>(Wq, gwpk + 0 * WSZ);
    repack_W<<<288, 256>>>(Wk, gwpk + 1 * WSZ);
    repack_W<<<288, 256>>>(Wv, gwpk + 2 * WSZ);
    repack_W<<<288, 256>>>(Wo, gwpk + 3 * WSZ);
    repack_A<<<6144, 256>>>(x, gapk);

    dim3 gg(NTILES, MTILES);   // (12, 128)
    mma_gemm<0><<<gg, 128>>>(gapk, gwpk + 0 * WSZ, bq, gq);
    mma_gemm<1><<<gg, 128>>>(gapk, gwpk + 1 * WSZ, bk, gkp);
    mma_gemm<2><<<gg, 128>>>(gapk, gwpk + 2 * WSZ, bv, gvp);

    dim3 ga(SEQ / 128, NHEAD, BATCH);   // (32, 12, 2)
    attn_kernel<<<ga, 256, ATTN_SMEM_BYTES>>>(gq, gkp, gvp, gctx);

    repack_A<<<6144, 256>>>(gctx, gapk);
    mma_gemm<3><<<gg, 128>>>(gapk, gwpk + 3 * WSZ, bo, out);
}

// round 9
// speedup vs baseline: 7.8415x; 1.1617x over previous
#include <cuda_runtime.h>
#include <cuda_fp16.h>
#include <cstdint>
#include <cstddef>

// ---------------------------------------------------------------------------
// MSA fp32: B=2, S=4096, D=768, H=12, dk=64 — fp16 mma.sync (m16n8k16).
// Accuracy scheme (calibrated R4/R5/R8): A-side hi/lo split in GEMMs,
// W/K/Q/P/V single fp16 (predicted rel_err ~5.5e-4 < 1e-3).
//   repack_W4        4x W -> single fp16 B-fragment tiles (one launch)
//   repack_A(x)      x -> hi/lo fp16 A-fragment tiles
//   mma_gemm<Q/K/V>  Q fp32 [B,H,S,64]; K fp16 frags; V fp16 frags
//   attn_kernel      flash attention, 128q/CTA, 8 warps, P in regs,
//                    epilogue writes ctx PACKED (hi/lo A-frag) directly
//   mma_gemm<OUT>    out = ctx_packed @ Wo + bo
// ---------------------------------------------------------------------------

#define D_MODEL 768
#define NHEAD   12
#define DK      64
#define BATCH   2
#define SEQ     4096
#define MROWS   8192
#define KT16    48      // 768/16
#define NTILES  12
#define MTILES  128

__device__ float    g_Q  [BATCH * NHEAD * SEQ * DK];
__device__ unsigned g_Kp [BATCH * NHEAD * 64 * 2048];   // fp16 packed words
__device__ unsigned g_Vp [BATCH * NHEAD * 64 * 2048];   // fp16 packed words
__device__ unsigned g_Apk[(size_t)MROWS * D_MODEL];     // hi/lo A words (x, then ctx)
__device__ unsigned g_Wpk[4 * D_MODEL * D_MODEL / 2];   // fp16 B words x4

// ---------------------------------------------------------------------------
// helpers
// ---------------------------------------------------------------------------
__device__ __forceinline__ unsigned pk(float first, float second) {
    unsigned r;
    asm("cvt.rn.f16x2.f32 %0, %1, %2;" : "=r"(r) : "f"(second), "f"(first));
    return r;
}
__device__ __forceinline__ void hsplit(float x, float& hi, float& lo) {
    hi = __half2float(__float2half_rn(x));
    lo = x - hi;
}
__device__ __forceinline__ void mma_f16(float d[4], const unsigned a[4],
                                        const unsigned b[2]) {
    asm volatile(
        "mma.sync.aligned.m16n8k16.row.col.f32.f16.f16.f32 "
        "{%0,%1,%2,%3}, {%4,%5,%6,%7}, {%8,%9}, {%0,%1,%2,%3};"
        : "+f"(d[0]), "+f"(d[1]), "+f"(d[2]), "+f"(d[3])
        : "r"(a[0]), "r"(a[1]), "r"(a[2]), "r"(a[3]), "r"(b[0]), "r"(b[1]));
}
__device__ __forceinline__ void cp_async16(unsigned s_addr, const void* g_ptr) {
    asm volatile("cp.async.cg.shared.global [%0], [%1], 16;"
                 :: "r"(s_addr), "l"(g_ptr) : "memory");
}
__device__ __forceinline__ void cp_commit() {
    asm volatile("cp.async.commit_group;" ::: "memory");
}
__device__ __forceinline__ void cp_wait0() {
    asm volatile("cp.async.wait_group 0;" ::: "memory");
}
__device__ __forceinline__ unsigned smem_u32(const void* p) {
    unsigned a;
    asm("{ .reg .u64 t; cvta.to.shared.u64 t, %1; cvt.u32.u64 %0, t; }"
        : "=r"(a) : "l"(p));
    return a;
}

// ---------------------------------------------------------------------------
// repack_A: [8192,768] fp32 -> per-(64m x 16k) tile hi/lo A-frag words.
// Tile block = 1024 words: [hi 512][lo 512]; hi word addr within 512:
//   wq*128 + lane*4 + reg, lane=(q&7)*4+(p&3), reg=(q>>3)+2*(p>>2), p=k-pair.
// ---------------------------------------------------------------------------
__global__ void __launch_bounds__(256) repack_A(const float* __restrict__ A,
                                                unsigned* __restrict__ dst) {
    int idx = blockIdx.x * 256 + threadIdx.x;     // one float4 each
    int m  = idx / 192;
    int k4 = (idx % 192) * 4;
    float4 v = *(const float4*)&A[(size_t)m * D_MODEL + k4];
    float vv[4] = {v.x, v.y, v.z, v.w};
    int mtile = m >> 6, wq = (m & 63) >> 4, q = m & 15;
    int kt = k4 >> 4;
    size_t base = ((size_t)(mtile * KT16 + kt)) * 1024 + wq * 128;
#pragma unroll
    for (int pp = 0; pp < 2; pp++) {
        float h0, l0, h1, l1;
        hsplit(vv[2 * pp],     h0, l0);
        hsplit(vv[2 * pp + 1], h1, l1);
        int p = ((k4 & 15) >> 1) + pp;
        int reg = (q >> 3) + 2 * (p >> 2);
        int lane = (q & 7) * 4 + (p & 3);
        size_t a = base + lane * 4 + reg;
        dst[a]       = pk(h0, h1);
        dst[a + 512] = pk(l0, l1);
    }
}

// ---------------------------------------------------------------------------
// repack_W4: all 4 weights -> single fp16 B-frag tiles. blockIdx.y = weight.
// Tile block = 512 words; addr: nb*64 + lane*2 + reg,
//   lane = (n&7)*4 + (p&3), reg = p>>2, p = (k&15)>>1.
// ---------------------------------------------------------------------------
__global__ void __launch_bounds__(256) repack_W4(
    const float* __restrict__ W0, const float* __restrict__ W1,
    const float* __restrict__ W2, const float* __restrict__ W3,
    unsigned* __restrict__ dst_all)
{
    const float* Ws[4] = {W0, W1, W2, W3};
    const float* W = Ws[blockIdx.y];
    unsigned* dst = dst_all + (size_t)blockIdx.y * (D_MODEL * D_MODEL / 2);

    int idx = blockIdx.x * 256 + threadIdx.x;     // (k-pair, n-float4)
    int kp = idx / 192;
    int k  = kp * 2;
    int n4 = (idx % 192) * 4;
    float4 va = *(const float4*)&W[(size_t)k * D_MODEL + n4];
    float4 vb = *(const float4*)&W[(size_t)(k + 1) * D_MODEL + n4];
    float aa[4] = {va.x, va.y, va.z, va.w};
    float bb[4] = {vb.x, vb.y, vb.z, vb.w};
    int kt = k >> 4;
    int p = (k & 15) >> 1, reg = p >> 2, t = p & 3;
#pragma unroll
    for (int j = 0; j < 4; j++) {
        int n = n4 + j;
        int ntile = n >> 6, nb = (n & 63) >> 3, g = n & 7;
        size_t a = ((size_t)(kt * NTILES + ntile)) * 512 +
                   nb * 64 + (g * 4 + t) * 2 + reg;
        dst[a] = pk(aa[j], bb[j]);
    }
}

// ---------------------------------------------------------------------------
// mma GEMM: C[8192,768] = A @ W + bias. CTA 64m x 64n, 4 warps, BK=32,
// double-buffered cp.async. 2 mma streams (A hi/lo x W fp16).
// MODE: 0=Q fp32, 1=K packed fp16, 2=V packed fp16, 3=row-major fp32.
// ---------------------------------------------------------------------------
template <int MODE>
__global__ void __launch_bounds__(128) mma_gemm(
    const unsigned* __restrict__ Apk, const unsigned* __restrict__ Bpk,
    const float* __restrict__ bias, void* __restrict__ Cv)
{
    __shared__ unsigned As[2][2048];
    __shared__ unsigned Bs[2][1024];

    const int tid = threadIdx.x;
    const int lane = tid & 31;
    const int w = tid >> 5;
    const int g = lane >> 2;
    const int qg = lane & 3;
    const int ntile = blockIdx.x;
    const int mtile = blockIdx.y;

    float c[8][4];
#pragma unroll
    for (int nt = 0; nt < 8; nt++)
#pragma unroll
        for (int j = 0; j < 4; j++) c[nt][j] = 0.0f;

    unsigned sA[2] = {smem_u32(&As[0][0]), smem_u32(&As[1][0])};
    unsigned sB[2] = {smem_u32(&Bs[0][0]), smem_u32(&Bs[1][0])};

#define GEMM_ISSUE(IT)                                                        \
    do {                                                                      \
        int _b = (IT) & 1;                                                    \
        const uint4* _ga = (const uint4*)(Apk +                               \
            ((size_t)(mtile * KT16 + (IT) * 2)) * 1024);                      \
        cp_async16(sA[_b] + tid * 16,        _ga + tid);                      \
        cp_async16(sA[_b] + tid * 16 + 2048, _ga + 128 + tid);                \
        cp_async16(sA[_b] + tid * 16 + 4096, _ga + 256 + tid);                \
        cp_async16(sA[_b] + tid * 16 + 6144, _ga + 384 + tid);                \
        const uint4* _gb0 = (const uint4*)(Bpk +                              \
            ((size_t)((IT) * 2 * NTILES + ntile)) * 512);                     \
        const uint4* _gb1 = (const uint4*)(Bpk +                              \
            ((size_t)(((IT) * 2 + 1) * NTILES + ntile)) * 512);               \
        cp_async16(sB[_b] + tid * 16,        _gb0 + tid);                     \
        cp_async16(sB[_b] + tid * 16 + 2048, _gb1 + tid);                     \
        cp_commit();                                                          \
    } while (0)

    GEMM_ISSUE(0);

    for (int it = 0; it < 24; it++) {
        cp_wait0();
        __syncthreads();
        if (it + 1 < 24) GEMM_ISSUE(it + 1);
        const int buf = it & 1;
#pragma unroll
        for (int kt2 = 0; kt2 < 2; kt2++) {
            const unsigned* Ab = &As[buf][kt2 * 1024 + w * 128];
            uint4 ah4 = *(const uint4*)&Ab[lane * 4];
            uint4 al4 = *(const uint4*)&Ab[512 + lane * 4];
            unsigned ah[4] = {ah4.x, ah4.y, ah4.z, ah4.w};
            unsigned al[4] = {al4.x, al4.y, al4.z, al4.w};
            const unsigned* Bb = &Bs[buf][kt2 * 512];
#pragma unroll
            for (int nt = 0; nt < 8; nt++) {
                uint2 bh2 = *(const uint2*)&Bb[nt * 64 + lane * 2];
                unsigned bh[2] = {bh2.x, bh2.y};
                mma_f16(c[nt], ah, bh);
                mma_f16(c[nt], al, bh);
            }
        }
        __syncthreads();
    }

    // ---- epilogue ----
    if (MODE == 0 || MODE == 3) {
        float* C = (float*)Cv;
#pragma unroll
        for (int nt = 0; nt < 8; nt++)
#pragma unroll
            for (int j = 0; j < 4; j++) {
                int m = mtile * 64 + w * 16 + g + ((j >= 2) ? 8 : 0);
                int n_local = nt * 8 + 2 * qg + (j & 1);
                float v = c[nt][j] + bias[ntile * 64 + n_local];
                if (MODE == 0) {
                    int b = m >> 12, s = m & 4095;
                    C[(size_t)(((b * NHEAD + ntile) << 12) + s) * DK + n_local] = v;
                } else {
                    C[(size_t)m * D_MODEL + ntile * 64 + n_local] = v;
                }
            }
    } else if (MODE == 1) {
        unsigned* C = (unsigned*)Cv;
        int b = mtile >> 6, keytile = mtile & 63;
        size_t base = ((size_t)(b * NHEAD + ntile) * 64 + keytile) * 2048;
#pragma unroll
        for (int nt = 0; nt < 8; nt++)
#pragma unroll
            for (int dlt = 0; dlt < 2; dlt++) {
                int klocal = w * 16 + g + 8 * dlt;
                float x = c[nt][2 * dlt]     + bias[ntile * 64 + nt * 8 + 2 * qg];
                float y = c[nt][2 * dlt + 1] + bias[ntile * 64 + nt * 8 + 2 * qg + 1];
                size_t idx = (size_t)(((nt >> 1) * 8 + (klocal >> 3)) * 64 +
                             ((klocal & 7) * 4 + qg) * 2 + (nt & 1));
                C[base + idx] = pk(x, y);
            }
    } else {   // MODE 2: V packed single fp16, pair adjacent keys via shfl
        unsigned* C = (unsigned*)Cv;
        int b = mtile >> 6, keytile = mtile & 63;
        size_t base = ((size_t)(b * NHEAD + ntile) * 64 + keytile) * 2048;
#pragma unroll
        for (int nt = 0; nt < 8; nt++)
#pragma unroll
            for (int dlt = 0; dlt < 2; dlt++)
#pragma unroll
                for (int j = 0; j < 2; j++) {
                    int d = nt * 8 + 2 * qg + j;
                    float x = c[nt][2 * dlt + j] + bias[ntile * 64 + d];
                    float y = __shfl_xor_sync(0xffffffffu, x, 4);
                    if (!(g & 1)) {
                        size_t idx = (size_t)((w * 8 + nt) * 64 +
                                     ((2 * qg + j) * 4 + (g >> 1)) * 2 + dlt);
                        C[base + idx] = pk(x, y);
                    }
                }
    }
#undef GEMM_ISSUE
}

// ---------------------------------------------------------------------------
// flash attention: 256 thr (8 warps), 128 q/CTA, 64 keys/iter, fp16 mma.
// Q single fp16 (scores 1 mma); K, V fp16 pre-packed; cp.async double-buffer.
// Epilogue writes ctx PACKED hi/lo A-frag into g_Apk (no fp32 ctx, no repack).
// smem (words): Q 0..4095, K bufs 4096/6144, V bufs 8192/10240.
// Total 12288 words = 48KB.
// ---------------------------------------------------------------------------
#define W_Q  0
#define W_K0 4096
#define W_V0 8192
#define ATTN_SMEM_BYTES (12288 * 4)

__global__ void __launch_bounds__(256) attn_kernel(
    const float* __restrict__ Q, const unsigned* __restrict__ Kp,
    const unsigned* __restrict__ Vp, unsigned* __restrict__ ctxp)
{
    extern __shared__ unsigned smw[];
    const int tid  = threadIdx.x;
    const int lane = tid & 31;
    const int w    = tid >> 5;    // 0..7
    const int g    = lane >> 2;
    const int qg   = lane & 3;

    const int q0 = blockIdx.x * 128;
    const int h  = blockIdx.y;
    const int b  = blockIdx.z;
    const float*    Qb = Q  + (size_t)(b * NHEAD + h) * SEQ * DK;
    const unsigned* Kh = Kp + (size_t)(b * NHEAD + h) * 64 * 2048;
    const unsigned* Vh = Vp + (size_t)(b * NHEAD + h) * 64 * 2048;

    unsigned smK = smem_u32(smw) + W_K0 * 4;
    unsigned smV = smem_u32(smw) + W_V0 * 4;

#define ATTN_ISSUE(KT)                                                        \
    do {                                                                      \
        int _b2 = (KT) & 1;                                                   \
        const uint4* _gk = (const uint4*)(Kh + (size_t)(KT) * 2048);          \
        const uint4* _gv = (const uint4*)(Vh + (size_t)(KT) * 2048);          \
        unsigned _sk = smK + _b2 * 8192;                                      \
        unsigned _sv = smV + _b2 * 8192;                                      \
        _Pragma("unroll")                                                     \
        for (int _i = 0; _i < 2; _i++)                                        \
            cp_async16(_sk + (_i * 256 + tid) * 16, _gk + _i * 256 + tid);    \
        _Pragma("unroll")                                                     \
        for (int _i = 0; _i < 2; _i++)                                        \
            cp_async16(_sv + (_i * 256 + tid) * 16, _gv + _i * 256 + tid);    \
        cp_commit();                                                          \
    } while (0)

    // ---- pack Q (single fp16, scaled 1/8): 128 rows ----
#pragma unroll
    for (int i = 0; i < 8; i++) {
        int idx = i * 256 + tid;
        int q  = idx >> 4;              // 0..127
        int d0 = (idx & 15) * 4;
        float4 v = *(const float4*)&Qb[(size_t)(q0 + q) * DK + d0];
        float vv[4] = {v.x * 0.125f, v.y * 0.125f, v.z * 0.125f, v.w * 0.125f};
        int wq = q >> 4, qr = q & 15, ks = d0 >> 4;
        int base = (wq * 4 + ks) * 128;
#pragma unroll
        for (int pp = 0; pp < 2; pp++) {
            int p = ((d0 & 15) >> 1) + pp;
            int reg = (qr >> 3) + 2 * (p >> 2);
            int ln = (qr & 7) * 4 + (p & 3);
            smw[W_Q + base + ln * 4 + reg] = pk(vv[2 * pp], vv[2 * pp + 1]);
        }
    }

    ATTN_ISSUE(0);

    float m0 = -1e30f, m1 = -1e30f, l0 = 0.0f, l1 = 0.0f;
    float o[8][4];
#pragma unroll
    for (int nt = 0; nt < 8; nt++)
#pragma unroll
        for (int j = 0; j < 4; j++) o[nt][j] = 0.0f;

    for (int kt = 0; kt < SEQ / 64; kt++) {
        cp_wait0();
        __syncthreads();
        if (kt + 1 < SEQ / 64) ATTN_ISSUE(kt + 1);

        const int kbuf = W_K0 + (kt & 1) * 2048;
        const int vbuf = W_V0 + (kt & 1) * 2048;

        // ---- scores: 1 mma per (ks, nt) ----
        float s[8][4];
#pragma unroll
        for (int nt = 0; nt < 8; nt++)
#pragma unroll
            for (int j = 0; j < 4; j++) s[nt][j] = 0.0f;

#pragma unroll
        for (int ks = 0; ks < 4; ks++) {
            uint4 ah4 = *(const uint4*)&smw[W_Q + (w * 4 + ks) * 128 + lane * 4];
            unsigned ah[4] = {ah4.x, ah4.y, ah4.z, ah4.w};
#pragma unroll
            for (int nt = 0; nt < 8; nt++) {
                uint2 bh2 = *(const uint2*)&smw[kbuf + (ks * 8 + nt) * 64 + lane * 2];
                unsigned bh[2] = {bh2.x, bh2.y};
                mma_f16(s[nt], ah, bh);
            }
        }

        // ---- online softmax (registers + quad shuffles) ----
        float mx0 = -1e30f, mx1 = -1e30f;
#pragma unroll
        for (int nt = 0; nt < 8; nt++) {
            mx0 = fmaxf(mx0, fmaxf(s[nt][0], s[nt][1]));
            mx1 = fmaxf(mx1, fmaxf(s[nt][2], s[nt][3]));
        }
        mx0 = fmaxf(mx0, __shfl_xor_sync(0xffffffffu, mx0, 1));
        mx0 = fmaxf(mx0, __shfl_xor_sync(0xffffffffu, mx0, 2));
        mx1 = fmaxf(mx1, __shfl_xor_sync(0xffffffffu, mx1, 1));
        mx1 = fmaxf(mx1, __shfl_xor_sync(0xffffffffu, mx1, 2));

        float mn0 = fmaxf(m0, mx0), mn1 = fmaxf(m1, mx1);
        float al0 = __expf(m0 - mn0), al1 = __expf(m1 - mn1);
        m0 = mn0; m1 = mn1;

        float rs0 = 0.0f, rs1 = 0.0f;
#pragma unroll
        for (int nt = 0; nt < 8; nt++) {
            s[nt][0] = __expf(s[nt][0] - mn0);
            s[nt][1] = __expf(s[nt][1] - mn0);
            s[nt][2] = __expf(s[nt][2] - mn1);
            s[nt][3] = __expf(s[nt][3] - mn1);
            rs0 += s[nt][0] + s[nt][1];
            rs1 += s[nt][2] + s[nt][3];
        }
        rs0 += __shfl_xor_sync(0xffffffffu, rs0, 1);
        rs0 += __shfl_xor_sync(0xffffffffu, rs0, 2);
        rs1 += __shfl_xor_sync(0xffffffffu, rs1, 1);
        rs1 += __shfl_xor_sync(0xffffffffu, rs1, 2);
        l0 = l0 * al0 + rs0;
        l1 = l1 * al1 + rs1;

#pragma unroll
        for (int nt = 0; nt < 8; nt++) {
            o[nt][0] *= al0; o[nt][1] *= al0;
            o[nt][2] *= al1; o[nt][3] *= al1;
        }

        // ---- O += P @ V : C-frag -> A-frag directly (k16 layout match) ----
#pragma unroll
        for (int ksv = 0; ksv < 4; ksv++) {
            unsigned a[4] = {pk(s[2 * ksv][0],     s[2 * ksv][1]),
                             pk(s[2 * ksv][2],     s[2 * ksv][3]),
                             pk(s[2 * ksv + 1][0], s[2 * ksv + 1][1]),
                             pk(s[2 * ksv + 1][2], s[2 * ksv + 1][3])};
#pragma unroll
            for (int nt = 0; nt < 8; nt++) {
                uint2 bv2 = *(const uint2*)&smw[vbuf + (ksv * 8 + nt) * 64 + lane * 2];
                unsigned bv[2] = {bv2.x, bv2.y};
                mma_f16(o[nt], a, bv);
            }
        }
    }

    // ---- epilogue: write ctx PACKED hi/lo A-frag (g_Apk layout) ----
    // row qa: qr=g (reg +0); row qa+8: qr=g+8 (reg +1). ln == lane.
    float inv0 = 1.0f / l0, inv1 = 1.0f / l1;
    const int qa = q0 + w * 16 + g;             // row for j=0,1
    const int mA = b * SEQ + qa;
    const int mtA = mA >> 6;                     // same tile for qa and qa+8
    const int wqA = (mA & 63) >> 4;
#pragma unroll
    for (int nt = 0; nt < 8; nt++) {
        int kk = h * DK + nt * 8 + 2 * qg;       // even k column
        int kt = kk >> 4;
        int p  = (kk & 15) >> 1;
        int regbase = 2 * (p >> 2);
        size_t base = ((size_t)(mtA * KT16 + kt)) * 1024 + wqA * 128 +
                      ((g & 7) * 4 + (p & 3)) * 4;
        float h0, l0v, h1, l1v;
        // row qa (reg = regbase + 0)
        hsplit(o[nt][0] * inv0, h0, l0v);
        hsplit(o[nt][1] * inv0, h1, l1v);
        ctxp[base + regbase]           = pk(h0, h1);
        ctxp[base + regbase + 512]     = pk(l0v, l1v);
        // row qa+8 (reg = regbase + 1)
        hsplit(o[nt][2] * inv1, h0, l0v);
        hsplit(o[nt][3] * inv1, h1, l1v);
        ctxp[base + regbase + 1]       = pk(h0, h1);
        ctxp[base + regbase + 1 + 512] = pk(l0v, l1v);
    }
#undef ATTN_ISSUE
}

// ---------------------------------------------------------------------------
// Launch
// ---------------------------------------------------------------------------
extern "C" void kernel_launch(void* const* d_in, const int* in_sizes, int n_in,
                              void* d_out, int out_size)
{
    const float* x  = (const float*)d_in[0];
    const float* Wq = (const float*)d_in[1];
    const float* bq = (const float*)d_in[2];
    const float* Wk = (const float*)d_in[3];
    const float* bk = (const float*)d_in[4];
    const float* Wv = (const float*)d_in[5];
    const float* bv = (const float*)d_in[6];
    const float* Wo = (const float*)d_in[7];
    const float* bo = (const float*)d_in[8];
    float* out = (float*)d_out;

    float* gq;
    unsigned *gkp, *gvp, *gapk, *gwpk;
    cudaGetSymbolAddress((void**)&gq,   g_Q);
    cudaGetSymbolAddress((void**)&gkp,  g_Kp);
    cudaGetSymbolAddress((void**)&gvp,  g_Vp);
    cudaGetSymbolAddress((void**)&gapk, g_Apk);
    cudaGetSymbolAddress((void**)&gwpk, g_Wpk);

    cudaFuncSetAttribute(attn_kernel,
                         cudaFuncAttributeMaxDynamicSharedMemorySize,
                         ATTN_SMEM_BYTES);

    const size_t WSZ = (size_t)D_MODEL * D_MODEL / 2;   // words per packed W

    dim3 gw(288, 4);
    repack_W4<<<gw, 256>>>(Wq, Wk, Wv, Wo, gwpk);
    repack_A<<<6144, 256>>>(x, gapk);

    dim3 gg(NTILES, MTILES);   // (12, 128)
    mma_gemm<0><<<gg, 128>>>(gapk, gwpk + 0 * WSZ, bq, gq);
    mma_gemm<1><<<gg, 128>>>(gapk, gwpk + 1 * WSZ, bk, gkp);
    mma_gemm<2><<<gg, 128>>>(gapk, gwpk + 2 * WSZ, bv, gvp);

    dim3 ga(SEQ / 128, NHEAD, BATCH);   // (32, 12, 2)
    attn_kernel<<<ga, 256, ATTN_SMEM_BYTES>>>(gq, gkp, gvp, gapk);

    mma_gemm<3><<<gg, 128>>>(gapk, gwpk + 3 * WSZ, bo, out);
}

// round 10
// speedup vs baseline: 8.5617x; 1.0918x over previous
#include <cuda_runtime.h>
#include <cuda_fp16.h>
#include <cstdint>
#include <cstddef>

// ---------------------------------------------------------------------------
// MSA fp32: B=2, S=4096, D=768, H=12, dk=64 — fp16 mma.sync (m16n8k16).
// Accuracy (calibrated R4/R5/R8/R9): x hi/lo packed; Q/K/V projections use
// single A-stream (their outputs are fp16-rounded anyway); out-proj 2-stream.
// Q written by its GEMM directly in attention fragment layout (log2-scaled).
//   repack_W4        4x W -> fp16 B-fragment tiles (one launch)
//   repack_A(x)      x -> hi/lo fp16 A-fragment tiles
//   mma_gemm<0,1>    Q packed fp16 attn-layout (scaled 0.125*log2e)
//   mma_gemm<1,1>    K packed fp16 frags;  mma_gemm<2,1> V packed fp16 frags
//   attn_kernel      flash attention, exp2-domain softmax, P in regs,
//                    epilogue writes ctx PACKED (hi/lo A-frag) into g_Apk
//   mma_gemm<3,2>    out = ctx_packed @ Wo + bo (2-stream)
// ---------------------------------------------------------------------------

#define D_MODEL 768
#define NHEAD   12
#define DK      64
#define BATCH   2
#define SEQ     4096
#define MROWS   8192
#define KT16    48      // 768/16
#define NTILES  12
#define MTILES  128

__device__ unsigned g_Qp [BATCH * NHEAD * 32 * 4096];   // Q fp16 attn frags
__device__ unsigned g_Kp [BATCH * NHEAD * 64 * 2048];   // K fp16 packed words
__device__ unsigned g_Vp [BATCH * NHEAD * 64 * 2048];   // V fp16 packed words
__device__ unsigned g_Apk[(size_t)MROWS * D_MODEL];     // hi/lo A words (x/ctx)
__device__ unsigned g_Wpk[4 * D_MODEL * D_MODEL / 2];   // fp16 B words x4

// ---------------------------------------------------------------------------
// helpers
// ---------------------------------------------------------------------------
__device__ __forceinline__ unsigned pk(float first, float second) {
    unsigned r;
    asm("cvt.rn.f16x2.f32 %0, %1, %2;" : "=r"(r) : "f"(second), "f"(first));
    return r;
}
__device__ __forceinline__ void hsplit(float x, float& hi, float& lo) {
    hi = __half2float(__float2half_rn(x));
    lo = x - hi;
}
__device__ __forceinline__ float ex2(float x) {
    float r;
    asm("ex2.approx.f32 %0, %1;" : "=f"(r) : "f"(x));
    return r;
}
__device__ __forceinline__ void mma_f16(float d[4], const unsigned a[4],
                                        const unsigned b[2]) {
    asm volatile(
        "mma.sync.aligned.m16n8k16.row.col.f32.f16.f16.f32 "
        "{%0,%1,%2,%3}, {%4,%5,%6,%7}, {%8,%9}, {%0,%1,%2,%3};"
        : "+f"(d[0]), "+f"(d[1]), "+f"(d[2]), "+f"(d[3])
        : "r"(a[0]), "r"(a[1]), "r"(a[2]), "r"(a[3]), "r"(b[0]), "r"(b[1]));
}
__device__ __forceinline__ void cp_async16(unsigned s_addr, const void* g_ptr) {
    asm volatile("cp.async.cg.shared.global [%0], [%1], 16;"
                 :: "r"(s_addr), "l"(g_ptr) : "memory");
}
__device__ __forceinline__ void cp_commit() {
    asm volatile("cp.async.commit_group;" ::: "memory");
}
__device__ __forceinline__ void cp_wait0() {
    asm volatile("cp.async.wait_group 0;" ::: "memory");
}
__device__ __forceinline__ unsigned smem_u32(const void* p) {
    unsigned a;
    asm("{ .reg .u64 t; cvta.to.shared.u64 t, %1; cvt.u32.u64 %0, t; }"
        : "=r"(a) : "l"(p));
    return a;
}

// ---------------------------------------------------------------------------
// repack_A: [8192,768] fp32 -> per-(64m x 16k) tile hi/lo A-frag words.
// ---------------------------------------------------------------------------
__global__ void __launch_bounds__(256) repack_A(const float* __restrict__ A,
                                                unsigned* __restrict__ dst) {
    int idx = blockIdx.x * 256 + threadIdx.x;     // one float4 each
    int m  = idx / 192;
    int k4 = (idx % 192) * 4;
    float4 v = *(const float4*)&A[(size_t)m * D_MODEL + k4];
    float vv[4] = {v.x, v.y, v.z, v.w};
    int mtile = m >> 6, wq = (m & 63) >> 4, q = m & 15;
    int kt = k4 >> 4;
    size_t base = ((size_t)(mtile * KT16 + kt)) * 1024 + wq * 128;
#pragma unroll
    for (int pp = 0; pp < 2; pp++) {
        float h0, l0, h1, l1;
        hsplit(vv[2 * pp],     h0, l0);
        hsplit(vv[2 * pp + 1], h1, l1);
        int p = ((k4 & 15) >> 1) + pp;
        int reg = (q >> 3) + 2 * (p >> 2);
        int lane = (q & 7) * 4 + (p & 3);
        size_t a = base + lane * 4 + reg;
        dst[a]       = pk(h0, h1);
        dst[a + 512] = pk(l0, l1);
    }
}

// ---------------------------------------------------------------------------
// repack_W4: all 4 weights -> single fp16 B-frag tiles. blockIdx.y = weight.
// ---------------------------------------------------------------------------
__global__ void __launch_bounds__(256) repack_W4(
    const float* __restrict__ W0, const float* __restrict__ W1,
    const float* __restrict__ W2, const float* __restrict__ W3,
    unsigned* __restrict__ dst_all)
{
    const float* Ws[4] = {W0, W1, W2, W3};
    const float* W = Ws[blockIdx.y];
    unsigned* dst = dst_all + (size_t)blockIdx.y * (D_MODEL * D_MODEL / 2);

    int idx = blockIdx.x * 256 + threadIdx.x;     // (k-pair, n-float4)
    int kp = idx / 192;
    int k  = kp * 2;
    int n4 = (idx % 192) * 4;
    float4 va = *(const float4*)&W[(size_t)k * D_MODEL + n4];
    float4 vb = *(const float4*)&W[(size_t)(k + 1) * D_MODEL + n4];
    float aa[4] = {va.x, va.y, va.z, va.w};
    float bb[4] = {vb.x, vb.y, vb.z, vb.w};
    int kt = k >> 4;
    int p = (k & 15) >> 1, reg = p >> 2, t = p & 3;
#pragma unroll
    for (int j = 0; j < 4; j++) {
        int n = n4 + j;
        int ntile = n >> 6, nb = (n & 63) >> 3, g = n & 7;
        size_t a = ((size_t)(kt * NTILES + ntile)) * 512 +
                   nb * 64 + (g * 4 + t) * 2 + reg;
        dst[a] = pk(aa[j], bb[j]);
    }
}

// ---------------------------------------------------------------------------
// mma GEMM: C[8192,768] = A @ W + bias. CTA 64m x 64n, 4 warps, BK=32,
// double-buffered cp.async. STREAMS = A-side mma streams (1: hi only).
// MODE: 0=Q packed attn-frag (log2-scaled), 1=K packed, 2=V packed, 3=fp32.
// ---------------------------------------------------------------------------
template <int MODE, int STREAMS>
__global__ void __launch_bounds__(128) mma_gemm(
    const unsigned* __restrict__ Apk, const unsigned* __restrict__ Bpk,
    const float* __restrict__ bias, void* __restrict__ Cv)
{
    __shared__ unsigned As[2][STREAMS * 1024];
    __shared__ unsigned Bs[2][1024];

    const int tid = threadIdx.x;
    const int lane = tid & 31;
    const int w = tid >> 5;
    const int g = lane >> 2;
    const int qg = lane & 3;
    const int ntile = blockIdx.x;
    const int mtile = blockIdx.y;

    float c[8][4];
#pragma unroll
    for (int nt = 0; nt < 8; nt++)
#pragma unroll
        for (int j = 0; j < 4; j++) c[nt][j] = 0.0f;

    unsigned sA[2] = {smem_u32(&As[0][0]), smem_u32(&As[1][0])};
    unsigned sB[2] = {smem_u32(&Bs[0][0]), smem_u32(&Bs[1][0])};

#define GEMM_ISSUE(IT)                                                        \
    do {                                                                      \
        int _b = (IT) & 1;                                                    \
        const uint4* _ga = (const uint4*)(Apk +                               \
            ((size_t)(mtile * KT16 + (IT) * 2)) * 1024);                      \
        if (STREAMS == 2) {                                                   \
            cp_async16(sA[_b] + tid * 16,        _ga + tid);                  \
            cp_async16(sA[_b] + tid * 16 + 2048, _ga + 128 + tid);            \
            cp_async16(sA[_b] + tid * 16 + 4096, _ga + 256 + tid);            \
            cp_async16(sA[_b] + tid * 16 + 6144, _ga + 384 + tid);            \
        } else {  /* hi halves only: words 0..511 and 1024..1535 */           \
            cp_async16(sA[_b] + tid * 16,        _ga + tid);                  \
            cp_async16(sA[_b] + tid * 16 + 2048, _ga + 256 + tid);            \
        }                                                                     \
        const uint4* _gb0 = (const uint4*)(Bpk +                              \
            ((size_t)((IT) * 2 * NTILES + ntile)) * 512);                     \
        const uint4* _gb1 = (const uint4*)(Bpk +                              \
            ((size_t)(((IT) * 2 + 1) * NTILES + ntile)) * 512);               \
        cp_async16(sB[_b] + tid * 16,        _gb0 + tid);                     \
        cp_async16(sB[_b] + tid * 16 + 2048, _gb1 + tid);                     \
        cp_commit();                                                          \
    } while (0)

    GEMM_ISSUE(0);

    for (int it = 0; it < 24; it++) {
        cp_wait0();
        __syncthreads();
        if (it + 1 < 24) GEMM_ISSUE(it + 1);
        const int buf = it & 1;
#pragma unroll
        for (int kt2 = 0; kt2 < 2; kt2++) {
            const unsigned* Ab = &As[buf][kt2 * (STREAMS * 512) + w * 128];
            uint4 ah4 = *(const uint4*)&Ab[lane * 4];
            unsigned ah[4] = {ah4.x, ah4.y, ah4.z, ah4.w};
            unsigned al[4];
            if (STREAMS == 2) {
                uint4 al4 = *(const uint4*)&Ab[512 + lane * 4];
                al[0] = al4.x; al[1] = al4.y; al[2] = al4.z; al[3] = al4.w;
            }
            const unsigned* Bb = &Bs[buf][kt2 * 512];
#pragma unroll
            for (int nt = 0; nt < 8; nt++) {
                uint2 bh2 = *(const uint2*)&Bb[nt * 64 + lane * 2];
                unsigned bh[2] = {bh2.x, bh2.y};
                mma_f16(c[nt], ah, bh);
                if (STREAMS == 2) mma_f16(c[nt], al, bh);
            }
        }
        __syncthreads();
    }

    // ---- epilogue ----
    if (MODE == 3) {
        float* C = (float*)Cv;
#pragma unroll
        for (int nt = 0; nt < 8; nt++)
#pragma unroll
            for (int j = 0; j < 4; j++) {
                int m = mtile * 64 + w * 16 + g + ((j >= 2) ? 8 : 0);
                int n_local = nt * 8 + 2 * qg + (j & 1);
                C[(size_t)m * D_MODEL + ntile * 64 + n_local] =
                    c[nt][j] + bias[ntile * 64 + n_local];
            }
    } else if (MODE == 0) {
        // Q packed fp16 in attention fragment layout, scaled 0.125*log2(e)
        unsigned* C = (unsigned*)Cv;
        const float sc = 0.125f * 1.44269504f;
        int b = mtile >> 6;
        int qt = (mtile & 63) >> 1;
        int wq = (mtile & 1) * 4 + w;
        size_t tb = ((size_t)(b * NHEAD + ntile) * 32 + qt) * 4096 +
                    (size_t)wq * 512;
#pragma unroll
        for (int nt = 0; nt < 8; nt++) {
            float bx = bias[ntile * 64 + nt * 8 + 2 * qg];
            float by = bias[ntile * 64 + nt * 8 + 2 * qg + 1];
#pragma unroll
            for (int dlt = 0; dlt < 2; dlt++) {
                float x = (c[nt][2 * dlt]     + bx) * sc;
                float y = (c[nt][2 * dlt + 1] + by) * sc;
                C[tb + (nt >> 1) * 128 + lane * 4 + 2 * (nt & 1) + dlt] =
                    pk(x, y);
            }
        }
    } else if (MODE == 1) {
        unsigned* C = (unsigned*)Cv;
        int b = mtile >> 6, keytile = mtile & 63;
        size_t base = ((size_t)(b * NHEAD + ntile) * 64 + keytile) * 2048;
#pragma unroll
        for (int nt = 0; nt < 8; nt++)
#pragma unroll
            for (int dlt = 0; dlt < 2; dlt++) {
                int klocal = w * 16 + g + 8 * dlt;
                float x = c[nt][2 * dlt]     + bias[ntile * 64 + nt * 8 + 2 * qg];
                float y = c[nt][2 * dlt + 1] + bias[ntile * 64 + nt * 8 + 2 * qg + 1];
                size_t idx = (size_t)(((nt >> 1) * 8 + (klocal >> 3)) * 64 +
                             ((klocal & 7) * 4 + qg) * 2 + (nt & 1));
                C[base + idx] = pk(x, y);
            }
    } else {   // MODE 2: V packed single fp16, pair adjacent keys via shfl
        unsigned* C = (unsigned*)Cv;
        int b = mtile >> 6, keytile = mtile & 63;
        size_t base = ((size_t)(b * NHEAD + ntile) * 64 + keytile) * 2048;
#pragma unroll
        for (int nt = 0; nt < 8; nt++)
#pragma unroll
            for (int dlt = 0; dlt < 2; dlt++)
#pragma unroll
                for (int j = 0; j < 2; j++) {
                    int d = nt * 8 + 2 * qg + j;
                    float x = c[nt][2 * dlt + j] + bias[ntile * 64 + d];
                    float y = __shfl_xor_sync(0xffffffffu, x, 4);
                    if (!(g & 1)) {
                        size_t idx = (size_t)((w * 8 + nt) * 64 +
                                     ((2 * qg + j) * 4 + (g >> 1)) * 2 + dlt);
                        C[base + idx] = pk(x, y);
                    }
                }
    }
#undef GEMM_ISSUE
}

// ---------------------------------------------------------------------------
// flash attention: 256 thr (8 warps), 128 q/CTA, 64 keys/iter, fp16 mma.
// Q pre-packed (log2-scaled) loaded via cp.async; exp2-domain softmax.
// Epilogue writes ctx PACKED hi/lo A-frag into g_Apk.
// smem (words): Q 0..4095, K bufs 4096/6144, V bufs 8192/10240. 48KB.
// ---------------------------------------------------------------------------
#define W_Q  0
#define W_K0 4096
#define W_V0 8192
#define ATTN_SMEM_BYTES (12288 * 4)

__global__ void __launch_bounds__(256) attn_kernel(
    const unsigned* __restrict__ Qp, const unsigned* __restrict__ Kp,
    const unsigned* __restrict__ Vp, unsigned* __restrict__ ctxp)
{
    extern __shared__ unsigned smw[];
    const int tid  = threadIdx.x;
    const int lane = tid & 31;
    const int w    = tid >> 5;    // 0..7
    const int g    = lane >> 2;
    const int qg   = lane & 3;

    const int q0 = blockIdx.x * 128;
    const int h  = blockIdx.y;
    const int b  = blockIdx.z;
    const unsigned* Qh = Qp + ((size_t)(b * NHEAD + h) * 32 + blockIdx.x) * 4096;
    const unsigned* Kh = Kp + (size_t)(b * NHEAD + h) * 64 * 2048;
    const unsigned* Vh = Vp + (size_t)(b * NHEAD + h) * 64 * 2048;

    unsigned smQ = smem_u32(smw) + W_Q * 4;
    unsigned smK = smem_u32(smw) + W_K0 * 4;
    unsigned smV = smem_u32(smw) + W_V0 * 4;

#define ATTN_ISSUE(KT)                                                        \
    do {                                                                      \
        int _b2 = (KT) & 1;                                                   \
        const uint4* _gk = (const uint4*)(Kh + (size_t)(KT) * 2048);          \
        const uint4* _gv = (const uint4*)(Vh + (size_t)(KT) * 2048);          \
        unsigned _sk = smK + _b2 * 8192;                                      \
        unsigned _sv = smV + _b2 * 8192;                                      \
        _Pragma("unroll")                                                     \
        for (int _i = 0; _i < 2; _i++)                                        \
            cp_async16(_sk + (_i * 256 + tid) * 16, _gk + _i * 256 + tid);    \
        _Pragma("unroll")                                                     \
        for (int _i = 0; _i < 2; _i++)                                        \
            cp_async16(_sv + (_i * 256 + tid) * 16, _gv + _i * 256 + tid);    \
        cp_commit();                                                          \
    } while (0)

    // ---- Q tile: straight async copy (pre-packed, pre-scaled) ----
#pragma unroll
    for (int i = 0; i < 4; i++)
        cp_async16(smQ + (unsigned)((i * 256 + tid) * 16),
                   (const uint4*)Qh + i * 256 + tid);
    cp_commit();

    ATTN_ISSUE(0);

    float m0 = -1e30f, m1 = -1e30f, l0 = 0.0f, l1 = 0.0f;
    float o[8][4];
#pragma unroll
    for (int nt = 0; nt < 8; nt++)
#pragma unroll
        for (int j = 0; j < 4; j++) o[nt][j] = 0.0f;

    for (int kt = 0; kt < SEQ / 64; kt++) {
        cp_wait0();
        __syncthreads();
        if (kt + 1 < SEQ / 64) ATTN_ISSUE(kt + 1);

        const int kbuf = W_K0 + (kt & 1) * 2048;
        const int vbuf = W_V0 + (kt & 1) * 2048;

        // ---- scores (log2 domain): 1 mma per (ks, nt) ----
        float s[8][4];
#pragma unroll
        for (int nt = 0; nt < 8; nt++)
#pragma unroll
            for (int j = 0; j < 4; j++) s[nt][j] = 0.0f;

#pragma unroll
        for (int ks = 0; ks < 4; ks++) {
            uint4 ah4 = *(const uint4*)&smw[W_Q + (w * 4 + ks) * 128 + lane * 4];
            unsigned ah[4] = {ah4.x, ah4.y, ah4.z, ah4.w};
#pragma unroll
            for (int nt = 0; nt < 8; nt++) {
                uint2 bh2 = *(const uint2*)&smw[kbuf + (ks * 8 + nt) * 64 + lane * 2];
                unsigned bh[2] = {bh2.x, bh2.y};
                mma_f16(s[nt], ah, bh);
            }
        }

        // ---- online softmax (exp2 domain, registers + quad shuffles) ----
        float mx0 = -1e30f, mx1 = -1e30f;
#pragma unroll
        for (int nt = 0; nt < 8; nt++) {
            mx0 = fmaxf(mx0, fmaxf(s[nt][0], s[nt][1]));
            mx1 = fmaxf(mx1, fmaxf(s[nt][2], s[nt][3]));
        }
        mx0 = fmaxf(mx0, __shfl_xor_sync(0xffffffffu, mx0, 1));
        mx0 = fmaxf(mx0, __shfl_xor_sync(0xffffffffu, mx0, 2));
        mx1 = fmaxf(mx1, __shfl_xor_sync(0xffffffffu, mx1, 1));
        mx1 = fmaxf(mx1, __shfl_xor_sync(0xffffffffu, mx1, 2));

        float mn0 = fmaxf(m0, mx0), mn1 = fmaxf(m1, mx1);
        float al0 = ex2(m0 - mn0), al1 = ex2(m1 - mn1);
        m0 = mn0; m1 = mn1;

        float rs0 = 0.0f, rs1 = 0.0f;
#pragma unroll
        for (int nt = 0; nt < 8; nt++) {
            s[nt][0] = ex2(s[nt][0] - mn0);
            s[nt][1] = ex2(s[nt][1] - mn0);
            s[nt][2] = ex2(s[nt][2] - mn1);
            s[nt][3] = ex2(s[nt][3] - mn1);
            rs0 += s[nt][0] + s[nt][1];
            rs1 += s[nt][2] + s[nt][3];
        }
        rs0 += __shfl_xor_sync(0xffffffffu, rs0, 1);
        rs0 += __shfl_xor_sync(0xffffffffu, rs0, 2);
        rs1 += __shfl_xor_sync(0xffffffffu, rs1, 1);
        rs1 += __shfl_xor_sync(0xffffffffu, rs1, 2);
        l0 = l0 * al0 + rs0;
        l1 = l1 * al1 + rs1;

#pragma unroll
        for (int nt = 0; nt < 8; nt++) {
            o[nt][0] *= al0; o[nt][1] *= al0;
            o[nt][2] *= al1; o[nt][3] *= al1;
        }

        // ---- O += P @ V : C-frag -> A-frag directly (k16 layout match) ----
#pragma unroll
        for (int ksv = 0; ksv < 4; ksv++) {
            unsigned a[4] = {pk(s[2 * ksv][0],     s[2 * ksv][1]),
                             pk(s[2 * ksv][2],     s[2 * ksv][3]),
                             pk(s[2 * ksv + 1][0], s[2 * ksv + 1][1]),
                             pk(s[2 * ksv + 1][2], s[2 * ksv + 1][3])};
#pragma unroll
            for (int nt = 0; nt < 8; nt++) {
                uint2 bv2 = *(const uint2*)&smw[vbuf + (ksv * 8 + nt) * 64 + lane * 2];
                unsigned bv[2] = {bv2.x, bv2.y};
                mma_f16(o[nt], a, bv);
            }
        }
    }

    // ---- epilogue: write ctx PACKED hi/lo A-frag (g_Apk layout) ----
    float inv0 = 1.0f / l0, inv1 = 1.0f / l1;
    const int qa = q0 + w * 16 + g;             // row for j=0,1
    const int mA = b * SEQ + qa;
    const int mtA = mA >> 6;
    const int wqA = (mA & 63) >> 4;
#pragma unroll
    for (int nt = 0; nt < 8; nt++) {
        int kk = h * DK + nt * 8 + 2 * qg;       // even k column
        int kt = kk >> 4;
        int p  = (kk & 15) >> 1;
        int regbase = 2 * (p >> 2);
        size_t base = ((size_t)(mtA * KT16 + kt)) * 1024 + wqA * 128 +
                      ((g & 7) * 4 + (p & 3)) * 4;
        float h0, l0v, h1, l1v;
        hsplit(o[nt][0] * inv0, h0, l0v);
        hsplit(o[nt][1] * inv0, h1, l1v);
        ctxp[base + regbase]           = pk(h0, h1);
        ctxp[base + regbase + 512]     = pk(l0v, l1v);
        hsplit(o[nt][2] * inv1, h0, l0v);
        hsplit(o[nt][3] * inv1, h1, l1v);
        ctxp[base + regbase + 1]       = pk(h0, h1);
        ctxp[base + regbase + 1 + 512] = pk(l0v, l1v);
    }
#undef ATTN_ISSUE
}

// ---------------------------------------------------------------------------
// Launch
// ---------------------------------------------------------------------------
extern "C" void kernel_launch(void* const* d_in, const int* in_sizes, int n_in,
                              void* d_out, int out_size)
{
    const float* x  = (const float*)d_in[0];
    const float* Wq = (const float*)d_in[1];
    const float* bq = (const float*)d_in[2];
    const float* Wk = (const float*)d_in[3];
    const float* bk = (const float*)d_in[4];
    const float* Wv = (const float*)d_in[5];
    const float* bv = (const float*)d_in[6];
    const float* Wo = (const float*)d_in[7];
    const float* bo = (const float*)d_in[8];
    float* out = (float*)d_out;

    unsigned *gqp, *gkp, *gvp, *gapk, *gwpk;
    cudaGetSymbolAddress((void**)&gqp,  g_Qp);
    cudaGetSymbolAddress((void**)&gkp,  g_Kp);
    cudaGetSymbolAddress((void**)&gvp,  g_Vp);
    cudaGetSymbolAddress((void**)&gapk, g_Apk);
    cudaGetSymbolAddress((void**)&gwpk, g_Wpk);

    cudaFuncSetAttribute(attn_kernel,
                         cudaFuncAttributeMaxDynamicSharedMemorySize,
                         ATTN_SMEM_BYTES);

    const size_t WSZ = (size_t)D_MODEL * D_MODEL / 2;   // words per packed W

    dim3 gw(288, 4);
    repack_W4<<<gw, 256>>>(Wq, Wk, Wv, Wo, gwpk);
    repack_A<<<6144, 256>>>(x, gapk);

    dim3 gg(NTILES, MTILES);   // (12, 128)
    mma_gemm<0, 1><<<gg, 128>>>(gapk, gwpk + 0 * WSZ, bq, gqp);
    mma_gemm<1, 1><<<gg, 128>>>(gapk, gwpk + 1 * WSZ, bk, gkp);
    mma_gemm<2, 1><<<gg, 128>>>(gapk, gwpk + 2 * WSZ, bv, gvp);

    dim3 ga(SEQ / 128, NHEAD, BATCH);   // (32, 12, 2)
    attn_kernel<<<ga, 256, ATTN_SMEM_BYTES>>>(gqp, gkp, gvp, gapk);

    mma_gemm<3, 2><<<gg, 128>>>(gapk, gwpk + 3 * WSZ, bo, out);
}

// round 11
// speedup vs baseline: 9.2774x; 1.0836x over previous
#include <cuda_runtime.h>
#include <cuda_fp16.h>
#include <cstdint>
#include <cstddef>

// ---------------------------------------------------------------------------
// MSA fp32: B=2, S=4096, D=768, H=12, dk=64 — fp16 mma.sync (m16n8k16).
// R11: GEMM BK=64 (12 iters), attention KT=128 (32 iters, one softmax/128key).
// Numerics identical to R10 (rel_err ~5.5e-4).
// ---------------------------------------------------------------------------

#define D_MODEL 768
#define NHEAD   12
#define DK      64
#define BATCH   2
#define SEQ     4096
#define MROWS   8192
#define KT16    48      // 768/16
#define NTILES  12
#define MTILES  128

__device__ unsigned g_Qp [BATCH * NHEAD * 32 * 4096];   // Q fp16 attn frags
__device__ unsigned g_Kp [BATCH * NHEAD * 64 * 2048];   // K fp16 packed words
__device__ unsigned g_Vp [BATCH * NHEAD * 64 * 2048];   // V fp16 packed words
__device__ unsigned g_Apk[(size_t)MROWS * D_MODEL];     // hi/lo A words (x/ctx)
__device__ unsigned g_Wpk[4 * D_MODEL * D_MODEL / 2];   // fp16 B words x4

// ---------------------------------------------------------------------------
// helpers
// ---------------------------------------------------------------------------
__device__ __forceinline__ unsigned pk(float first, float second) {
    unsigned r;
    asm("cvt.rn.f16x2.f32 %0, %1, %2;" : "=r"(r) : "f"(second), "f"(first));
    return r;
}
__device__ __forceinline__ void hsplit(float x, float& hi, float& lo) {
    hi = __half2float(__float2half_rn(x));
    lo = x - hi;
}
__device__ __forceinline__ float ex2(float x) {
    float r;
    asm("ex2.approx.f32 %0, %1;" : "=f"(r) : "f"(x));
    return r;
}
__device__ __forceinline__ void mma_f16(float d[4], const unsigned a[4],
                                        const unsigned b[2]) {
    asm volatile(
        "mma.sync.aligned.m16n8k16.row.col.f32.f16.f16.f32 "
        "{%0,%1,%2,%3}, {%4,%5,%6,%7}, {%8,%9}, {%0,%1,%2,%3};"
        : "+f"(d[0]), "+f"(d[1]), "+f"(d[2]), "+f"(d[3])
        : "r"(a[0]), "r"(a[1]), "r"(a[2]), "r"(a[3]), "r"(b[0]), "r"(b[1]));
}
__device__ __forceinline__ void cp_async16(unsigned s_addr, const void* g_ptr) {
    asm volatile("cp.async.cg.shared.global [%0], [%1], 16;"
                 :: "r"(s_addr), "l"(g_ptr) : "memory");
}
__device__ __forceinline__ void cp_commit() {
    asm volatile("cp.async.commit_group;" ::: "memory");
}
__device__ __forceinline__ void cp_wait0() {
    asm volatile("cp.async.wait_group 0;" ::: "memory");
}
__device__ __forceinline__ unsigned smem_u32(const void* p) {
    unsigned a;
    asm("{ .reg .u64 t; cvta.to.shared.u64 t, %1; cvt.u32.u64 %0, t; }"
        : "=r"(a) : "l"(p));
    return a;
}

// ---------------------------------------------------------------------------
// repack_A: [8192,768] fp32 -> per-(64m x 16k) tile hi/lo A-frag words.
// ---------------------------------------------------------------------------
__global__ void __launch_bounds__(256) repack_A(const float* __restrict__ A,
                                                unsigned* __restrict__ dst) {
    int idx = blockIdx.x * 256 + threadIdx.x;     // one float4 each
    int m  = idx / 192;
    int k4 = (idx % 192) * 4;
    float4 v = *(const float4*)&A[(size_t)m * D_MODEL + k4];
    float vv[4] = {v.x, v.y, v.z, v.w};
    int mtile = m >> 6, wq = (m & 63) >> 4, q = m & 15;
    int kt = k4 >> 4;
    size_t base = ((size_t)(mtile * KT16 + kt)) * 1024 + wq * 128;
#pragma unroll
    for (int pp = 0; pp < 2; pp++) {
        float h0, l0, h1, l1;
        hsplit(vv[2 * pp],     h0, l0);
        hsplit(vv[2 * pp + 1], h1, l1);
        int p = ((k4 & 15) >> 1) + pp;
        int reg = (q >> 3) + 2 * (p >> 2);
        int lane = (q & 7) * 4 + (p & 3);
        size_t a = base + lane * 4 + reg;
        dst[a]       = pk(h0, h1);
        dst[a + 512] = pk(l0, l1);
    }
}

// ---------------------------------------------------------------------------
// repack_W4: all 4 weights -> single fp16 B-frag tiles. blockIdx.y = weight.
// ---------------------------------------------------------------------------
__global__ void __launch_bounds__(256) repack_W4(
    const float* __restrict__ W0, const float* __restrict__ W1,
    const float* __restrict__ W2, const float* __restrict__ W3,
    unsigned* __restrict__ dst_all)
{
    const float* Ws[4] = {W0, W1, W2, W3};
    const float* W = Ws[blockIdx.y];
    unsigned* dst = dst_all + (size_t)blockIdx.y * (D_MODEL * D_MODEL / 2);

    int idx = blockIdx.x * 256 + threadIdx.x;     // (k-pair, n-float4)
    int kp = idx / 192;
    int k  = kp * 2;
    int n4 = (idx % 192) * 4;
    float4 va = *(const float4*)&W[(size_t)k * D_MODEL + n4];
    float4 vb = *(const float4*)&W[(size_t)(k + 1) * D_MODEL + n4];
    float aa[4] = {va.x, va.y, va.z, va.w};
    float bb[4] = {vb.x, vb.y, vb.z, vb.w};
    int kt = k >> 4;
    int p = (k & 15) >> 1, reg = p >> 2, t = p & 3;
#pragma unroll
    for (int j = 0; j < 4; j++) {
        int n = n4 + j;
        int ntile = n >> 6, nb = (n & 63) >> 3, g = n & 7;
        size_t a = ((size_t)(kt * NTILES + ntile)) * 512 +
                   nb * 64 + (g * 4 + t) * 2 + reg;
        dst[a] = pk(aa[j], bb[j]);
    }
}

// ---------------------------------------------------------------------------
// mma GEMM: C[8192,768] = A @ W + bias. CTA 64m x 64n, 4 warps, BK=64,
// double-buffered cp.async. STREAMS = A-side mma streams (1: hi only).
// MODE: 0=Q packed attn-frag (log2-scaled), 1=K packed, 2=V packed, 3=fp32.
// ---------------------------------------------------------------------------
template <int MODE, int STREAMS>
__global__ void __launch_bounds__(128) mma_gemm(
    const unsigned* __restrict__ Apk, const unsigned* __restrict__ Bpk,
    const float* __restrict__ bias, void* __restrict__ Cv)
{
    __shared__ unsigned As[2][STREAMS * 2048];
    __shared__ unsigned Bs[2][2048];

    const int tid = threadIdx.x;
    const int lane = tid & 31;
    const int w = tid >> 5;
    const int g = lane >> 2;
    const int qg = lane & 3;
    const int ntile = blockIdx.x;
    const int mtile = blockIdx.y;

    float c[8][4];
#pragma unroll
    for (int nt = 0; nt < 8; nt++)
#pragma unroll
        for (int j = 0; j < 4; j++) c[nt][j] = 0.0f;

    unsigned sA[2] = {smem_u32(&As[0][0]), smem_u32(&As[1][0])};
    unsigned sB[2] = {smem_u32(&Bs[0][0]), smem_u32(&Bs[1][0])};

#define GEMM_ISSUE(IT)                                                        \
    do {                                                                      \
        int _b = (IT) & 1;                                                    \
        const uint4* _ga = (const uint4*)(Apk +                               \
            ((size_t)(mtile * KT16 + (IT) * 4)) * 1024);                      \
        if (STREAMS == 2) {                                                   \
            _Pragma("unroll")                                                 \
            for (int _j = 0; _j < 8; _j++)                                    \
                cp_async16(sA[_b] + tid * 16 + _j * 2048,                     \
                           _ga + _j * 128 + tid);                             \
        } else {  /* hi halves only of 4 k16-tiles */                         \
            _Pragma("unroll")                                                 \
            for (int _j = 0; _j < 4; _j++)                                    \
                cp_async16(sA[_b] + tid * 16 + _j * 2048,                     \
                           _ga + _j * 256 + tid);                             \
        }                                                                     \
        _Pragma("unroll")                                                     \
        for (int _j = 0; _j < 4; _j++) {                                      \
            const uint4* _gb = (const uint4*)(Bpk +                           \
                ((size_t)(((IT) * 4 + _j) * NTILES + ntile)) * 512);          \
            cp_async16(sB[_b] + tid * 16 + _j * 2048, _gb + tid);             \
        }                                                                     \
        cp_commit();                                                          \
    } while (0)

    GEMM_ISSUE(0);

    for (int it = 0; it < 12; it++) {
        cp_wait0();
        __syncthreads();
        if (it + 1 < 12) GEMM_ISSUE(it + 1);
        const int buf = it & 1;
#pragma unroll
        for (int kt2 = 0; kt2 < 4; kt2++) {
            const unsigned* Ab = &As[buf][kt2 * (STREAMS * 512) + w * 128];
            uint4 ah4 = *(const uint4*)&Ab[lane * 4];
            unsigned ah[4] = {ah4.x, ah4.y, ah4.z, ah4.w};
            unsigned al[4];
            if (STREAMS == 2) {
                uint4 al4 = *(const uint4*)&Ab[512 + lane * 4];
                al[0] = al4.x; al[1] = al4.y; al[2] = al4.z; al[3] = al4.w;
            }
            const unsigned* Bb = &Bs[buf][kt2 * 512];
#pragma unroll
            for (int nt = 0; nt < 8; nt++) {
                uint2 bh2 = *(const uint2*)&Bb[nt * 64 + lane * 2];
                unsigned bh[2] = {bh2.x, bh2.y};
                mma_f16(c[nt], ah, bh);
                if (STREAMS == 2) mma_f16(c[nt], al, bh);
            }
        }
        __syncthreads();
    }

    // ---- epilogue ----
    if (MODE == 3) {
        float* C = (float*)Cv;
#pragma unroll
        for (int nt = 0; nt < 8; nt++)
#pragma unroll
            for (int j = 0; j < 4; j++) {
                int m = mtile * 64 + w * 16 + g + ((j >= 2) ? 8 : 0);
                int n_local = nt * 8 + 2 * qg + (j & 1);
                C[(size_t)m * D_MODEL + ntile * 64 + n_local] =
                    c[nt][j] + bias[ntile * 64 + n_local];
            }
    } else if (MODE == 0) {
        // Q packed fp16 in attention fragment layout, scaled 0.125*log2(e)
        unsigned* C = (unsigned*)Cv;
        const float sc = 0.125f * 1.44269504f;
        int b = mtile >> 6;
        int qt = (mtile & 63) >> 1;
        int wq = (mtile & 1) * 4 + w;
        size_t tb = ((size_t)(b * NHEAD + ntile) * 32 + qt) * 4096 +
                    (size_t)wq * 512;
#pragma unroll
        for (int nt = 0; nt < 8; nt++) {
            float bx = bias[ntile * 64 + nt * 8 + 2 * qg];
            float by = bias[ntile * 64 + nt * 8 + 2 * qg + 1];
#pragma unroll
            for (int dlt = 0; dlt < 2; dlt++) {
                float x = (c[nt][2 * dlt]     + bx) * sc;
                float y = (c[nt][2 * dlt + 1] + by) * sc;
                C[tb + (nt >> 1) * 128 + lane * 4 + 2 * (nt & 1) + dlt] =
                    pk(x, y);
            }
        }
    } else if (MODE == 1) {
        unsigned* C = (unsigned*)Cv;
        int b = mtile >> 6, keytile = mtile & 63;
        size_t base = ((size_t)(b * NHEAD + ntile) * 64 + keytile) * 2048;
#pragma unroll
        for (int nt = 0; nt < 8; nt++)
#pragma unroll
            for (int dlt = 0; dlt < 2; dlt++) {
                int klocal = w * 16 + g + 8 * dlt;
                float x = c[nt][2 * dlt]     + bias[ntile * 64 + nt * 8 + 2 * qg];
                float y = c[nt][2 * dlt + 1] + bias[ntile * 64 + nt * 8 + 2 * qg + 1];
                size_t idx = (size_t)(((nt >> 1) * 8 + (klocal >> 3)) * 64 +
                             ((klocal & 7) * 4 + qg) * 2 + (nt & 1));
                C[base + idx] = pk(x, y);
            }
    } else {   // MODE 2: V packed single fp16, pair adjacent keys via shfl
        unsigned* C = (unsigned*)Cv;
        int b = mtile >> 6, keytile = mtile & 63;
        size_t base = ((size_t)(b * NHEAD + ntile) * 64 + keytile) * 2048;
#pragma unroll
        for (int nt = 0; nt < 8; nt++)
#pragma unroll
            for (int dlt = 0; dlt < 2; dlt++)
#pragma unroll
                for (int j = 0; j < 2; j++) {
                    int d = nt * 8 + 2 * qg + j;
                    float x = c[nt][2 * dlt + j] + bias[ntile * 64 + d];
                    float y = __shfl_xor_sync(0xffffffffu, x, 4);
                    if (!(g & 1)) {
                        size_t idx = (size_t)((w * 8 + nt) * 64 +
                                     ((2 * qg + j) * 4 + (g >> 1)) * 2 + dlt);
                        C[base + idx] = pk(x, y);
                    }
                }
    }
#undef GEMM_ISSUE
}

// ---------------------------------------------------------------------------
// flash attention: 256 thr (8 warps), 128 q/CTA, 128 keys/iter (32 iters),
// one softmax pass per 128 keys. Q pre-packed (log2-scaled); exp2 softmax.
// Epilogue writes ctx PACKED hi/lo A-frag into g_Apk.
// smem (words): Q 0..4095, K bufs 4096/8192 (4096 each), V bufs 12288/16384.
// Total 20480 words = 80KB.
// ---------------------------------------------------------------------------
#define W_Q  0
#define W_K0 4096
#define W_V0 12288
#define ATTN_SMEM_BYTES (20480 * 4)

__global__ void __launch_bounds__(256) attn_kernel(
    const unsigned* __restrict__ Qp, const unsigned* __restrict__ Kp,
    const unsigned* __restrict__ Vp, unsigned* __restrict__ ctxp)
{
    extern __shared__ unsigned smw[];
    const int tid  = threadIdx.x;
    const int lane = tid & 31;
    const int w    = tid >> 5;    // 0..7
    const int g    = lane >> 2;
    const int qg   = lane & 3;

    const int q0 = blockIdx.x * 128;
    const int h  = blockIdx.y;
    const int b  = blockIdx.z;
    const unsigned* Qh = Qp + ((size_t)(b * NHEAD + h) * 32 + blockIdx.x) * 4096;
    const unsigned* Kh = Kp + (size_t)(b * NHEAD + h) * 64 * 2048;
    const unsigned* Vh = Vp + (size_t)(b * NHEAD + h) * 64 * 2048;

    unsigned smQ = smem_u32(smw) + W_Q * 4;
    unsigned smK = smem_u32(smw) + W_K0 * 4;
    unsigned smV = smem_u32(smw) + W_V0 * 4;

    // 128 keys per issue: 4096 K words + 4096 V words (16KB each)
#define ATTN_ISSUE(KT)                                                        \
    do {                                                                      \
        int _b2 = (KT) & 1;                                                   \
        const uint4* _gk = (const uint4*)(Kh + (size_t)(KT) * 4096);          \
        const uint4* _gv = (const uint4*)(Vh + (size_t)(KT) * 4096);          \
        unsigned _sk = smK + _b2 * 16384;                                     \
        unsigned _sv = smV + _b2 * 16384;                                     \
        _Pragma("unroll")                                                     \
        for (int _i = 0; _i < 4; _i++)                                        \
            cp_async16(_sk + (_i * 256 + tid) * 16, _gk + _i * 256 + tid);    \
        _Pragma("unroll")                                                     \
        for (int _i = 0; _i < 4; _i++)                                        \
            cp_async16(_sv + (_i * 256 + tid) * 16, _gv + _i * 256 + tid);    \
        cp_commit();                                                          \
    } while (0)

    // ---- Q tile: straight async copy (pre-packed, pre-scaled) ----
#pragma unroll
    for (int i = 0; i < 4; i++)
        cp_async16(smQ + (unsigned)((i * 256 + tid) * 16),
                   (const uint4*)Qh + i * 256 + tid);
    cp_commit();

    ATTN_ISSUE(0);

    float m0 = -1e30f, m1 = -1e30f, l0 = 0.0f, l1 = 0.0f;
    float o[8][4];
#pragma unroll
    for (int nt = 0; nt < 8; nt++)
#pragma unroll
        for (int j = 0; j < 4; j++) o[nt][j] = 0.0f;

    for (int kt = 0; kt < SEQ / 128; kt++) {
        cp_wait0();
        __syncthreads();
        if (kt + 1 < SEQ / 128) ATTN_ISSUE(kt + 1);

        const int kbuf = W_K0 + (kt & 1) * 4096;
        const int vbuf = W_V0 + (kt & 1) * 4096;

        // ---- scores (log2 domain): 128 keys, s[16][4] ----
        float s[16][4];
#pragma unroll
        for (int nt = 0; nt < 16; nt++)
#pragma unroll
            for (int j = 0; j < 4; j++) s[nt][j] = 0.0f;

#pragma unroll
        for (int ks = 0; ks < 4; ks++) {
            uint4 ah4 = *(const uint4*)&smw[W_Q + (w * 4 + ks) * 128 + lane * 4];
            unsigned ah[4] = {ah4.x, ah4.y, ah4.z, ah4.w};
#pragma unroll
            for (int nt = 0; nt < 16; nt++) {
                uint2 bh2 = *(const uint2*)&smw[kbuf + (nt >> 3) * 2048 +
                                                (ks * 8 + (nt & 7)) * 64 + lane * 2];
                unsigned bh[2] = {bh2.x, bh2.y};
                mma_f16(s[nt], ah, bh);
            }
        }

        // ---- online softmax over 128 keys (exp2 domain) ----
        float mx0 = -1e30f, mx1 = -1e30f;
#pragma unroll
        for (int nt = 0; nt < 16; nt++) {
            mx0 = fmaxf(mx0, fmaxf(s[nt][0], s[nt][1]));
            mx1 = fmaxf(mx1, fmaxf(s[nt][2], s[nt][3]));
        }
        mx0 = fmaxf(mx0, __shfl_xor_sync(0xffffffffu, mx0, 1));
        mx0 = fmaxf(mx0, __shfl_xor_sync(0xffffffffu, mx0, 2));
        mx1 = fmaxf(mx1, __shfl_xor_sync(0xffffffffu, mx1, 1));
        mx1 = fmaxf(mx1, __shfl_xor_sync(0xffffffffu, mx1, 2));

        float mn0 = fmaxf(m0, mx0), mn1 = fmaxf(m1, mx1);
        float al0 = ex2(m0 - mn0), al1 = ex2(m1 - mn1);
        m0 = mn0; m1 = mn1;

        float rs0 = 0.0f, rs1 = 0.0f;
#pragma unroll
        for (int nt = 0; nt < 16; nt++) {
            s[nt][0] = ex2(s[nt][0] - mn0);
            s[nt][1] = ex2(s[nt][1] - mn0);
            s[nt][2] = ex2(s[nt][2] - mn1);
            s[nt][3] = ex2(s[nt][3] - mn1);
            rs0 += s[nt][0] + s[nt][1];
            rs1 += s[nt][2] + s[nt][3];
        }
        rs0 += __shfl_xor_sync(0xffffffffu, rs0, 1);
        rs0 += __shfl_xor_sync(0xffffffffu, rs0, 2);
        rs1 += __shfl_xor_sync(0xffffffffu, rs1, 1);
        rs1 += __shfl_xor_sync(0xffffffffu, rs1, 2);
        l0 = l0 * al0 + rs0;
        l1 = l1 * al1 + rs1;

#pragma unroll
        for (int nt = 0; nt < 8; nt++) {
            o[nt][0] *= al0; o[nt][1] *= al0;
            o[nt][2] *= al1; o[nt][3] *= al1;
        }

        // ---- O += P @ V over 128 keys ----
#pragma unroll
        for (int ksv = 0; ksv < 8; ksv++) {
            unsigned a[4] = {pk(s[2 * ksv][0],     s[2 * ksv][1]),
                             pk(s[2 * ksv][2],     s[2 * ksv][3]),
                             pk(s[2 * ksv + 1][0], s[2 * ksv + 1][1]),
                             pk(s[2 * ksv + 1][2], s[2 * ksv + 1][3])};
#pragma unroll
            for (int nt = 0; nt < 8; nt++) {
                uint2 bv2 = *(const uint2*)&smw[vbuf + (ksv >> 2) * 2048 +
                                                ((ksv & 3) * 8 + nt) * 64 + lane * 2];
                unsigned bv[2] = {bv2.x, bv2.y};
                mma_f16(o[nt], a, bv);
            }
        }
    }

    // ---- epilogue: write ctx PACKED hi/lo A-frag (g_Apk layout) ----
    float inv0 = 1.0f / l0, inv1 = 1.0f / l1;
    const int qa = q0 + w * 16 + g;             // row for j=0,1
    const int mA = b * SEQ + qa;
    const int mtA = mA >> 6;
    const int wqA = (mA & 63) >> 4;
#pragma unroll
    for (int nt = 0; nt < 8; nt++) {
        int kk = h * DK + nt * 8 + 2 * qg;       // even k column
        int kt = kk >> 4;
        int p  = (kk & 15) >> 1;
        int regbase = 2 * (p >> 2);
        size_t base = ((size_t)(mtA * KT16 + kt)) * 1024 + wqA * 128 +
                      ((g & 7) * 4 + (p & 3)) * 4;
        float h0, l0v, h1, l1v;
        hsplit(o[nt][0] * inv0, h0, l0v);
        hsplit(o[nt][1] * inv0, h1, l1v);
        ctxp[base + regbase]           = pk(h0, h1);
        ctxp[base + regbase + 512]     = pk(l0v, l1v);
        hsplit(o[nt][2] * inv1, h0, l0v);
        hsplit(o[nt][3] * inv1, h1, l1v);
        ctxp[base + regbase + 1]       = pk(h0, h1);
        ctxp[base + regbase + 1 + 512] = pk(l0v, l1v);
    }
#undef ATTN_ISSUE
}

// ---------------------------------------------------------------------------
// Launch
// ---------------------------------------------------------------------------
extern "C" void kernel_launch(void* const* d_in, const int* in_sizes, int n_in,
                              void* d_out, int out_size)
{
    const float* x  = (const float*)d_in[0];
    const float* Wq = (const float*)d_in[1];
    const float* bq = (const float*)d_in[2];
    const float* Wk = (const float*)d_in[3];
    const float* bk = (const float*)d_in[4];
    const float* Wv = (const float*)d_in[5];
    const float* bv = (const float*)d_in[6];
    const float* Wo = (const float*)d_in[7];
    const float* bo = (const float*)d_in[8];
    float* out = (float*)d_out;

    unsigned *gqp, *gkp, *gvp, *gapk, *gwpk;
    cudaGetSymbolAddress((void**)&gqp,  g_Qp);
    cudaGetSymbolAddress((void**)&gkp,  g_Kp);
    cudaGetSymbolAddress((void**)&gvp,  g_Vp);
    cudaGetSymbolAddress((void**)&gapk, g_Apk);
    cudaGetSymbolAddress((void**)&gwpk, g_Wpk);

    cudaFuncSetAttribute(attn_kernel,
                         cudaFuncAttributeMaxDynamicSharedMemorySize,
                         ATTN_SMEM_BYTES);

    const size_t WSZ = (size_t)D_MODEL * D_MODEL / 2;   // words per packed W

    dim3 gw(288, 4);
    repack_W4<<<gw, 256>>>(Wq, Wk, Wv, Wo, gwpk);
    repack_A<<<6144, 256>>>(x, gapk);

    dim3 gg(NTILES, MTILES);   // (12, 128)
    mma_gemm<0, 1><<<gg, 128>>>(gapk, gwpk + 0 * WSZ, bq, gqp);
    mma_gemm<1, 1><<<gg, 128>>>(gapk, gwpk + 1 * WSZ, bk, gkp);
    mma_gemm<2, 1><<<gg, 128>>>(gapk, gwpk + 2 * WSZ, bv, gvp);

    dim3 ga(SEQ / 128, NHEAD, BATCH);   // (32, 12, 2)
    attn_kernel<<<ga, 256, ATTN_SMEM_BYTES>>>(gqp, gkp, gvp, gapk);

    mma_gemm<3, 2><<<gg, 128>>>(gapk, gwpk + 3 * WSZ, bo, out);
}